// round 2
// baseline (speedup 1.0000x reference)
#include <cuda_runtime.h>
#include <cuda_bf16.h>

#define N_NODES 50000
#define N_EDGES 800000
#define NFEAT   512
#define H1      256
#define H2      128

// ---------------- scratch (device globals; no allocation allowed) ----------
__device__ float g_dinv[N_NODES];              // degree -> deg^{-1/2}
__device__ float g_h  [N_NODES * H1];          // x @ W1
__device__ float g_agg[N_NODES * H1];          // layer-1 aggregation, then relu(h1)
__device__ float g_h2 [N_NODES * H2];          // h1 @ W2

// ---------------- degree pipeline ------------------------------------------
__global__ void zero_deg_kernel() {
    int i = blockIdx.x * blockDim.x + threadIdx.x;
    if (i < N_NODES) g_dinv[i] = 0.0f;
}

__global__ void deg_count_kernel(const int* __restrict__ dst) {
    int e = blockIdx.x * blockDim.x + threadIdx.x;
    if (e < N_EDGES) atomicAdd(&g_dinv[dst[e]], 1.0f);
}

__global__ void deg_finalize_kernel() {
    int i = blockIdx.x * blockDim.x + threadIdx.x;
    if (i < N_NODES) {
        float d = g_dinv[i] + 1.0f;            // +1 self-loop
        g_dinv[i] = rsqrtf(d);                 // d >= 1 always
    }
}

// ---------------- SGEMM: C[M,N] = A[M,K] @ B[K,N] ---------------------------
// BM=BN=128, BK=8, 256 threads, 8x8 per-thread tile.
__global__ __launch_bounds__(256)
void sgemm128_kernel(const float* __restrict__ A, const float* __restrict__ B,
                     float* __restrict__ C, int M, int N, int K) {
    __shared__ float As[8][128];   // transposed: As[k][m]
    __shared__ float Bs[8][128];

    int tid = threadIdx.x;
    int m0 = blockIdx.x * 128;
    int n0 = blockIdx.y * 128;

    int tx = tid & 15;             // 0..15  -> n sub-tile
    int ty = tid >> 4;             // 0..15  -> m sub-tile

    // A tile load: 128x8 floats, one float4 per thread
    int a_row = tid >> 1;          // 0..127
    int a_col = (tid & 1) * 4;     // 0 or 4
    // B tile load: 8x128 floats, one float4 per thread
    int b_row = tid >> 5;          // 0..7
    int b_col = (tid & 31) * 4;    // 0..124

    bool a_valid = (m0 + a_row) < M;

    float acc[8][8];
#pragma unroll
    for (int i = 0; i < 8; i++)
#pragma unroll
        for (int j = 0; j < 8; j++) acc[i][j] = 0.0f;

    for (int k0 = 0; k0 < K; k0 += 8) {
        float4 av = make_float4(0.f, 0.f, 0.f, 0.f);
        if (a_valid)
            av = *(const float4*)(A + (size_t)(m0 + a_row) * K + k0 + a_col);
        As[a_col + 0][a_row] = av.x;
        As[a_col + 1][a_row] = av.y;
        As[a_col + 2][a_row] = av.z;
        As[a_col + 3][a_row] = av.w;

        float4 bv = *(const float4*)(B + (size_t)(k0 + b_row) * N + n0 + b_col);
        *(float4*)&Bs[b_row][b_col] = bv;

        __syncthreads();

#pragma unroll
        for (int kk = 0; kk < 8; kk++) {
            float ra[8], rb[8];
            *(float4*)&ra[0] = *(const float4*)&As[kk][ty * 8];
            *(float4*)&ra[4] = *(const float4*)&As[kk][ty * 8 + 4];
            *(float4*)&rb[0] = *(const float4*)&Bs[kk][tx * 8];
            *(float4*)&rb[4] = *(const float4*)&Bs[kk][tx * 8 + 4];
#pragma unroll
            for (int i = 0; i < 8; i++)
#pragma unroll
                for (int j = 0; j < 8; j++)
                    acc[i][j] = fmaf(ra[i], rb[j], acc[i][j]);
        }
        __syncthreads();
    }

#pragma unroll
    for (int i = 0; i < 8; i++) {
        int m = m0 + ty * 8 + i;
        if (m < M) {
            float* cp = C + (size_t)m * N + n0 + tx * 8;
            *(float4*)cp       = make_float4(acc[i][0], acc[i][1], acc[i][2], acc[i][3]);
            *(float4*)(cp + 4) = make_float4(acc[i][4], acc[i][5], acc[i][6], acc[i][7]);
        }
    }
}

// ---------------- self-loop init: agg[n,c] = h[n,c] * dinv[n]^2 (+bias opt) -
template <int C>
__global__ void init_selfloop_kernel(const float* __restrict__ h,
                                     float* __restrict__ agg,
                                     const float* __restrict__ bias) {
    int i4 = blockIdx.x * blockDim.x + threadIdx.x;          // float4 index
    const int C4 = C / 4;
    if (i4 >= N_NODES * C4) return;
    int n = i4 / C4;
    int c4 = i4 - n * C4;
    float di = g_dinv[n];
    float w = di * di;
    float4 v = ((const float4*)h)[i4];
    v.x *= w; v.y *= w; v.z *= w; v.w *= w;
    if (bias) {
        const float4 b = ((const float4*)bias)[c4];
        v.x += b.x; v.y += b.y; v.z += b.z; v.w += b.w;
    }
    ((float4*)agg)[i4] = v;
}

// ---------------- edge scatter: agg[dst] += h[src] * dinv[src]*dinv[dst] ----
template <int C>
__global__ void scatter_kernel(const int* __restrict__ src,
                               const int* __restrict__ dst,
                               const float* __restrict__ h,
                               float* __restrict__ agg) {
    int gw = (blockIdx.x * blockDim.x + threadIdx.x) >> 5;   // warp per edge
    int lane = threadIdx.x & 31;
    if (gw >= N_EDGES) return;
    int s = src[gw];
    int d = dst[gw];
    float norm = g_dinv[s] * g_dinv[d];
    const float4* hp = (const float4*)(h + (size_t)s * C);
    float* ap = agg + (size_t)d * C;
    const int C4 = C / 4;
#pragma unroll
    for (int i = lane; i < C4; i += 32) {
        float4 v = hp[i];
        atomicAdd(ap + 4 * i + 0, v.x * norm);
        atomicAdd(ap + 4 * i + 1, v.y * norm);
        atomicAdd(ap + 4 * i + 2, v.z * norm);
        atomicAdd(ap + 4 * i + 3, v.w * norm);
    }
}

// ---------------- bias + relu (layer 1 epilogue) ----------------------------
template <int C>
__global__ void bias_relu_kernel(float* __restrict__ agg,
                                 const float* __restrict__ bias) {
    int i4 = blockIdx.x * blockDim.x + threadIdx.x;
    const int C4 = C / 4;
    if (i4 >= N_NODES * C4) return;
    int c4 = i4 % C4;
    float4 v = ((float4*)agg)[i4];
    const float4 b = ((const float4*)bias)[c4];
    v.x = fmaxf(v.x + b.x, 0.f);
    v.y = fmaxf(v.y + b.y, 0.f);
    v.z = fmaxf(v.z + b.z, 0.f);
    v.w = fmaxf(v.w + b.w, 0.f);
    ((float4*)agg)[i4] = v;
}

// ---------------- launch ----------------------------------------------------
extern "C" void kernel_launch(void* const* d_in, const int* in_sizes, int n_in,
                              void* d_out, int out_size) {
    const float* x  = (const float*)d_in[0];
    const int*   ei = (const int*)d_in[1];     // int32: JAX x64 disabled
    const float* W1 = (const float*)d_in[2];
    const float* b1 = (const float*)d_in[3];
    const float* W2 = (const float*)d_in[4];
    const float* b2 = (const float*)d_in[5];
    float* out = (float*)d_out;

    const int* src = ei;
    const int* dst = ei + N_EDGES;

    float* g_dinv_p; cudaGetSymbolAddress((void**)&g_dinv_p, g_dinv);
    float* g_h_p;    cudaGetSymbolAddress((void**)&g_h_p,    g_h);
    float* g_agg_p;  cudaGetSymbolAddress((void**)&g_agg_p,  g_agg);
    float* g_h2_p;   cudaGetSymbolAddress((void**)&g_h2_p,   g_h2);

    // 1) degrees -> dinv
    zero_deg_kernel<<<(N_NODES + 255) / 256, 256>>>();
    deg_count_kernel<<<(N_EDGES + 255) / 256, 256>>>(dst);
    deg_finalize_kernel<<<(N_NODES + 255) / 256, 256>>>();

    // 2) h = x @ W1
    {
        dim3 grid((N_NODES + 127) / 128, H1 / 128);
        sgemm128_kernel<<<grid, 256>>>(x, W1, g_h_p, N_NODES, H1, NFEAT);
    }

    // 3) agg = selfloop(h) ; scatter edges ; h1 = relu(agg + b1)
    {
        int n4 = N_NODES * (H1 / 4);
        init_selfloop_kernel<H1><<<(n4 + 255) / 256, 256>>>(g_h_p, g_agg_p, nullptr);
        scatter_kernel<H1><<<(N_EDGES * 32 + 255) / 256, 256>>>(src, dst, g_h_p, g_agg_p);
        bias_relu_kernel<H1><<<(n4 + 255) / 256, 256>>>(g_agg_p, b1);
    }

    // 4) h2 = h1 @ W2
    {
        dim3 grid((N_NODES + 127) / 128, H2 / 128);
        sgemm128_kernel<<<grid, 256>>>(g_agg_p, W2, g_h2_p, N_NODES, H2, H1);
    }

    // 5) out = selfloop(h2) + b2 ; scatter edges (bias folded into init)
    {
        int n4 = N_NODES * (H2 / 4);
        init_selfloop_kernel<H2><<<(n4 + 255) / 256, 256>>>(g_h2_p, out, b2);
        scatter_kernel<H2><<<(N_EDGES * 32 + 255) / 256, 256>>>(src, dst, g_h2_p, out);
    }
}

// round 3
// speedup vs baseline: 1.5309x; 1.5309x over previous
#include <cuda_runtime.h>
#include <cuda_bf16.h>

#define N_NODES 50000
#define N_EDGES 800000
#define NFEAT   512
#define H1      256
#define H2      128

// ---------------- scratch (device globals; no allocation allowed) ----------
__device__ float g_dinv[N_NODES];              // degree -> deg^{-1/2}
__device__ float g_h  [N_NODES * H1];          // x @ W1
__device__ float g_agg[N_NODES * H1];          // layer-1 aggregation, then relu(h1)
__device__ float g_h2 [N_NODES * H2];          // h1 @ W2

// ---------------- helpers ---------------------------------------------------
__device__ __forceinline__ void red_add_v4(float* p, float4 v) {
    asm volatile("red.global.add.v4.f32 [%0], {%1, %2, %3, %4};"
                 :: "l"(p), "f"(v.x), "f"(v.y), "f"(v.z), "f"(v.w)
                 : "memory");
}

// ---------------- degree pipeline ------------------------------------------
__global__ void zero_deg_kernel() {
    int i = blockIdx.x * blockDim.x + threadIdx.x;
    if (i < N_NODES) g_dinv[i] = 0.0f;
}

__global__ void deg_count_kernel(const int* __restrict__ dst) {
    int e = blockIdx.x * blockDim.x + threadIdx.x;
    if (e < N_EDGES) atomicAdd(&g_dinv[dst[e]], 1.0f);
}

__global__ void deg_finalize_kernel() {
    int i = blockIdx.x * blockDim.x + threadIdx.x;
    if (i < N_NODES) {
        float d = g_dinv[i] + 1.0f;            // +1 self-loop
        g_dinv[i] = rsqrtf(d);                 // d >= 1 always
    }
}

// ---------------- SGEMM: C[M,N] = A[M,K] @ B[K,N] ---------------------------
// BM=BN=128, BK=8, 256 threads, 8x8 per-thread tile, register prefetch.
__global__ __launch_bounds__(256)
void sgemm128_kernel(const float* __restrict__ A, const float* __restrict__ B,
                     float* __restrict__ C, int M, int N, int K) {
    __shared__ float As[8][128];   // transposed: As[k][m]
    __shared__ float Bs[8][128];

    int tid = threadIdx.x;
    int m0 = blockIdx.x * 128;
    int n0 = blockIdx.y * 128;

    int tx = tid & 15;             // 0..15  -> n sub-tile
    int ty = tid >> 4;             // 0..15  -> m sub-tile

    // A tile load: 128x8 floats, one float4 per thread
    int a_row = tid >> 1;          // 0..127
    int a_col = (tid & 1) * 4;     // 0 or 4
    // B tile load: 8x128 floats, one float4 per thread
    int b_row = tid >> 5;          // 0..7
    int b_col = (tid & 31) * 4;    // 0..124

    bool a_valid = (m0 + a_row) < M;
    const float* a_ptr = A + (size_t)(m0 + a_row) * K + a_col;
    const float* b_ptr = B + (size_t)b_row * N + n0 + b_col;

    float acc[8][8];
#pragma unroll
    for (int i = 0; i < 8; i++)
#pragma unroll
        for (int j = 0; j < 8; j++) acc[i][j] = 0.0f;

    // prefetch first tiles into registers
    float4 av = make_float4(0.f, 0.f, 0.f, 0.f);
    if (a_valid) av = *(const float4*)a_ptr;
    float4 bv = *(const float4*)b_ptr;

    for (int k0 = 0; k0 < K; k0 += 8) {
        As[a_col + 0][a_row] = av.x;
        As[a_col + 1][a_row] = av.y;
        As[a_col + 2][a_row] = av.z;
        As[a_col + 3][a_row] = av.w;
        *(float4*)&Bs[b_row][b_col] = bv;
        __syncthreads();

        // issue next-tile loads BEFORE compute so latency overlaps FFMAs
        if (k0 + 8 < K) {
            if (a_valid) av = *(const float4*)(a_ptr + k0 + 8);
            bv = *(const float4*)(b_ptr + (size_t)(k0 + 8) * N);
        }

#pragma unroll
        for (int kk = 0; kk < 8; kk++) {
            float ra[8], rb[8];
            *(float4*)&ra[0] = *(const float4*)&As[kk][ty * 8];
            *(float4*)&ra[4] = *(const float4*)&As[kk][ty * 8 + 4];
            *(float4*)&rb[0] = *(const float4*)&Bs[kk][tx * 8];
            *(float4*)&rb[4] = *(const float4*)&Bs[kk][tx * 8 + 4];
#pragma unroll
            for (int i = 0; i < 8; i++)
#pragma unroll
                for (int j = 0; j < 8; j++)
                    acc[i][j] = fmaf(ra[i], rb[j], acc[i][j]);
        }
        __syncthreads();
    }

#pragma unroll
    for (int i = 0; i < 8; i++) {
        int m = m0 + ty * 8 + i;
        if (m < M) {
            float* cp = C + (size_t)m * N + n0 + tx * 8;
            *(float4*)cp       = make_float4(acc[i][0], acc[i][1], acc[i][2], acc[i][3]);
            *(float4*)(cp + 4) = make_float4(acc[i][4], acc[i][5], acc[i][6], acc[i][7]);
        }
    }
}

// ---------------- self-loop init: agg[n,c] = h[n,c] * dinv[n]^2 (+bias opt) -
template <int C>
__global__ void init_selfloop_kernel(const float* __restrict__ h,
                                     float* __restrict__ agg,
                                     const float* __restrict__ bias) {
    int i4 = blockIdx.x * blockDim.x + threadIdx.x;          // float4 index
    const int C4 = C / 4;
    if (i4 >= N_NODES * C4) return;
    int n = i4 / C4;
    int c4 = i4 - n * C4;
    float di = g_dinv[n];
    float w = di * di;
    float4 v = ((const float4*)h)[i4];
    v.x *= w; v.y *= w; v.z *= w; v.w *= w;
    if (bias) {
        const float4 b = ((const float4*)bias)[c4];
        v.x += b.x; v.y += b.y; v.z += b.z; v.w += b.w;
    }
    ((float4*)agg)[i4] = v;
}

// ---------------- edge scatter: agg[dst] += h[src] * dinv[src]*dinv[dst] ----
// warp per edge, one red.global.add.v4.f32 per float4 of the row
template <int C>
__global__ void scatter_kernel(const int* __restrict__ src,
                               const int* __restrict__ dst,
                               const float* __restrict__ h,
                               float* __restrict__ agg) {
    int gw = (blockIdx.x * blockDim.x + threadIdx.x) >> 5;   // warp per edge
    int lane = threadIdx.x & 31;
    if (gw >= N_EDGES) return;
    int s = src[gw];
    int d = dst[gw];
    float norm = g_dinv[s] * g_dinv[d];
    const float4* hp = (const float4*)(h + (size_t)s * C);
    float4* ap = (float4*)(agg + (size_t)d * C);
    const int C4 = C / 4;
#pragma unroll
    for (int i = lane; i < C4; i += 32) {
        float4 v = hp[i];
        v.x *= norm; v.y *= norm; v.z *= norm; v.w *= norm;
        red_add_v4((float*)(ap + i), v);
    }
}

// ---------------- bias + relu (layer 1 epilogue) ----------------------------
template <int C>
__global__ void bias_relu_kernel(float* __restrict__ agg,
                                 const float* __restrict__ bias) {
    int i4 = blockIdx.x * blockDim.x + threadIdx.x;
    const int C4 = C / 4;
    if (i4 >= N_NODES * C4) return;
    int c4 = i4 % C4;
    float4 v = ((float4*)agg)[i4];
    const float4 b = ((const float4*)bias)[c4];
    v.x = fmaxf(v.x + b.x, 0.f);
    v.y = fmaxf(v.y + b.y, 0.f);
    v.z = fmaxf(v.z + b.z, 0.f);
    v.w = fmaxf(v.w + b.w, 0.f);
    ((float4*)agg)[i4] = v;
}

// ---------------- launch ----------------------------------------------------
extern "C" void kernel_launch(void* const* d_in, const int* in_sizes, int n_in,
                              void* d_out, int out_size) {
    const float* x  = (const float*)d_in[0];
    const int*   ei = (const int*)d_in[1];     // int32: JAX x64 disabled
    const float* W1 = (const float*)d_in[2];
    const float* b1 = (const float*)d_in[3];
    const float* W2 = (const float*)d_in[4];
    const float* b2 = (const float*)d_in[5];
    float* out = (float*)d_out;

    const int* src = ei;
    const int* dst = ei + N_EDGES;

    float* g_h_p;    cudaGetSymbolAddress((void**)&g_h_p,    g_h);
    float* g_agg_p;  cudaGetSymbolAddress((void**)&g_agg_p,  g_agg);
    float* g_h2_p;   cudaGetSymbolAddress((void**)&g_h2_p,   g_h2);

    // 1) degrees -> dinv
    zero_deg_kernel<<<(N_NODES + 255) / 256, 256>>>();
    deg_count_kernel<<<(N_EDGES + 255) / 256, 256>>>(dst);
    deg_finalize_kernel<<<(N_NODES + 255) / 256, 256>>>();

    // 2) h = x @ W1
    {
        dim3 grid((N_NODES + 127) / 128, H1 / 128);
        sgemm128_kernel<<<grid, 256>>>(x, W1, g_h_p, N_NODES, H1, NFEAT);
    }

    // 3) agg = selfloop(h) ; scatter edges ; h1 = relu(agg + b1)
    {
        int n4 = N_NODES * (H1 / 4);
        init_selfloop_kernel<H1><<<(n4 + 255) / 256, 256>>>(g_h_p, g_agg_p, nullptr);
        scatter_kernel<H1><<<(N_EDGES * 32 + 255) / 256, 256>>>(src, dst, g_h_p, g_agg_p);
        bias_relu_kernel<H1><<<(n4 + 255) / 256, 256>>>(g_agg_p, b1);
    }

    // 4) h2 = h1 @ W2
    {
        dim3 grid((N_NODES + 127) / 128, H2 / 128);
        sgemm128_kernel<<<grid, 256>>>(g_agg_p, W2, g_h2_p, N_NODES, H2, H1);
    }

    // 5) out = selfloop(h2) + b2 ; scatter edges (bias folded into init)
    {
        int n4 = N_NODES * (H2 / 4);
        init_selfloop_kernel<H2><<<(n4 + 255) / 256, 256>>>(g_h2_p, out, b2);
        scatter_kernel<H2><<<(N_EDGES * 32 + 255) / 256, 256>>>(src, dst, g_h2_p, out);
    }
}

// round 4
// speedup vs baseline: 1.6356x; 1.0684x over previous
#include <cuda_runtime.h>
#include <cuda_bf16.h>

#define N_NODES 50000
#define N_EDGES 800000
#define NFEAT   512
#define H1      256
#define H2      128

typedef unsigned long long u64;

// ---------------- scratch (device globals; no allocation allowed) ----------
__device__ float g_dinv[N_NODES];              // degree -> deg^{-1/2}
__device__ float g_h  [N_NODES * H1];          // x @ W1
__device__ float g_agg[N_NODES * H1];          // layer-1 aggregation, then relu(h1)
__device__ float g_h2 [N_NODES * H2];          // h1 @ W2

// ---------------- helpers ---------------------------------------------------
__device__ __forceinline__ void red_add_v4(float* p, float4 v) {
    asm volatile("red.global.add.v4.f32 [%0], {%1, %2, %3, %4};"
                 :: "l"(p), "f"(v.x), "f"(v.y), "f"(v.z), "f"(v.w)
                 : "memory");
}
__device__ __forceinline__ u64 dup2(float v) {
    u64 r; asm("mov.b64 %0, {%1, %1};" : "=l"(r) : "f"(v)); return r;
}
__device__ __forceinline__ u64 ffma2(u64 a, u64 b, u64 c) {
    u64 d; asm("fma.rn.f32x2 %0, %1, %2, %3;" : "=l"(d) : "l"(a), "l"(b), "l"(c));
    return d;
}
__device__ __forceinline__ void unpack2(u64 v, float& lo, float& hi) {
    asm("mov.b64 {%0, %1}, %2;" : "=f"(lo), "=f"(hi) : "l"(v));
}

// ---------------- degree pipeline ------------------------------------------
__global__ void zero_deg_kernel() {
    int i = blockIdx.x * blockDim.x + threadIdx.x;
    if (i < N_NODES) g_dinv[i] = 0.0f;
}

__global__ void deg_count_kernel(const int* __restrict__ dst) {
    int e = blockIdx.x * blockDim.x + threadIdx.x;
    if (e < N_EDGES) atomicAdd(&g_dinv[dst[e]], 1.0f);
}

__global__ void deg_finalize_kernel() {
    int i = blockIdx.x * blockDim.x + threadIdx.x;
    if (i < N_NODES) {
        float d = g_dinv[i] + 1.0f;            // +1 self-loop
        g_dinv[i] = rsqrtf(d);                 // d >= 1 always
    }
}

// ---------------- SGEMM: C[M,N] = A[M,K] @ B[K,N] ---------------------------
// BM=BN=128, BK=8, 256 threads, 8x8 per-thread tile.
// Inner product via packed fma.rn.f32x2: accumulators paired along m.
__global__ __launch_bounds__(256)
void sgemm128_kernel(const float* __restrict__ A, const float* __restrict__ B,
                     float* __restrict__ C, int M, int N, int K) {
    __shared__ float As[8][128];   // transposed: As[k][m]
    __shared__ float Bs[8][128];

    int tid = threadIdx.x;
    int m0 = blockIdx.x * 128;
    int n0 = blockIdx.y * 128;

    int tx = tid & 15;             // 0..15  -> n sub-tile
    int ty = tid >> 4;             // 0..15  -> m sub-tile

    int a_row = tid >> 1;          // 0..127
    int a_col = (tid & 1) * 4;     // 0 or 4
    int b_row = tid >> 5;          // 0..7
    int b_col = (tid & 31) * 4;    // 0..124

    bool a_valid = (m0 + a_row) < M;
    const float* a_ptr = A + (size_t)(m0 + a_row) * K + a_col;
    const float* b_ptr = B + (size_t)b_row * N + n0 + b_col;

    // acc2[ip][j] = packed (C[2ip][j], C[2ip+1][j]) within the thread's 8x8 tile
    u64 acc2[4][8];
#pragma unroll
    for (int i = 0; i < 4; i++)
#pragma unroll
        for (int j = 0; j < 8; j++) acc2[i][j] = 0ULL;

    float4 av = make_float4(0.f, 0.f, 0.f, 0.f);
    if (a_valid) av = *(const float4*)a_ptr;
    float4 bv = *(const float4*)b_ptr;

    for (int k0 = 0; k0 < K; k0 += 8) {
        As[a_col + 0][a_row] = av.x;
        As[a_col + 1][a_row] = av.y;
        As[a_col + 2][a_row] = av.z;
        As[a_col + 3][a_row] = av.w;
        *(float4*)&Bs[b_row][b_col] = bv;
        __syncthreads();

        if (k0 + 8 < K) {
            if (a_valid) av = *(const float4*)(a_ptr + k0 + 8);
            bv = *(const float4*)(b_ptr + (size_t)(k0 + 8) * N);
        }

#pragma unroll
        for (int kk = 0; kk < 8; kk++) {
            // A pairs: contiguous m -> directly packed 64-bit loads
            u64 ap0, ap1, ap2, ap3;
            {
                const ulonglong2* app = (const ulonglong2*)&As[kk][ty * 8];
                ulonglong2 t0 = app[0];
                ulonglong2 t1 = app[1];
                ap0 = t0.x; ap1 = t0.y; ap2 = t1.x; ap3 = t1.y;
            }
            float rb[8];
            *(float4*)&rb[0] = *(const float4*)&Bs[kk][tx * 8];
            *(float4*)&rb[4] = *(const float4*)&Bs[kk][tx * 8 + 4];
#pragma unroll
            for (int j = 0; j < 8; j++) {
                u64 bd = dup2(rb[j]);
                acc2[0][j] = ffma2(ap0, bd, acc2[0][j]);
                acc2[1][j] = ffma2(ap1, bd, acc2[1][j]);
                acc2[2][j] = ffma2(ap2, bd, acc2[2][j]);
                acc2[3][j] = ffma2(ap3, bd, acc2[3][j]);
            }
        }
        __syncthreads();
    }

#pragma unroll
    for (int ip = 0; ip < 4; ip++) {
        float c0[8], c1[8];
#pragma unroll
        for (int j = 0; j < 8; j++) unpack2(acc2[ip][j], c0[j], c1[j]);
        int m_lo = m0 + ty * 8 + 2 * ip;
        if (m_lo < M) {
            float* cp = C + (size_t)m_lo * N + n0 + tx * 8;
            *(float4*)cp       = make_float4(c0[0], c0[1], c0[2], c0[3]);
            *(float4*)(cp + 4) = make_float4(c0[4], c0[5], c0[6], c0[7]);
        }
        if (m_lo + 1 < M) {
            float* cp = C + (size_t)(m_lo + 1) * N + n0 + tx * 8;
            *(float4*)cp       = make_float4(c1[0], c1[1], c1[2], c1[3]);
            *(float4*)(cp + 4) = make_float4(c1[4], c1[5], c1[6], c1[7]);
        }
    }
}

// ---------------- self-loop init: agg[n,c] = h[n,c] * dinv[n]^2 (+bias opt) -
template <int C>
__global__ void init_selfloop_kernel(const float* __restrict__ h,
                                     float* __restrict__ agg,
                                     const float* __restrict__ bias) {
    int i4 = blockIdx.x * blockDim.x + threadIdx.x;          // float4 index
    const int C4 = C / 4;
    if (i4 >= N_NODES * C4) return;
    int n = i4 / C4;
    int c4 = i4 - n * C4;
    float di = g_dinv[n];
    float w = di * di;
    float4 v = ((const float4*)h)[i4];
    v.x *= w; v.y *= w; v.z *= w; v.w *= w;
    if (bias) {
        const float4 b = ((const float4*)bias)[c4];
        v.x += b.x; v.y += b.y; v.z += b.z; v.w += b.w;
    }
    ((float4*)agg)[i4] = v;
}

// ---------------- edge scatter: agg[dst] += h[src] * dinv[src]*dinv[dst] ----
template <int C>
__global__ void scatter_kernel(const int* __restrict__ src,
                               const int* __restrict__ dst,
                               const float* __restrict__ h,
                               float* __restrict__ agg) {
    int gw = (blockIdx.x * blockDim.x + threadIdx.x) >> 5;   // warp per edge
    int lane = threadIdx.x & 31;
    if (gw >= N_EDGES) return;
    int s = src[gw];
    int d = dst[gw];
    float norm = g_dinv[s] * g_dinv[d];
    const float4* hp = (const float4*)(h + (size_t)s * C);
    float4* ap = (float4*)(agg + (size_t)d * C);
    const int C4 = C / 4;
#pragma unroll
    for (int i = lane; i < C4; i += 32) {
        float4 v = hp[i];
        v.x *= norm; v.y *= norm; v.z *= norm; v.w *= norm;
        red_add_v4((float*)(ap + i), v);
    }
}

// ---------------- bias + relu (layer 1 epilogue) ----------------------------
template <int C>
__global__ void bias_relu_kernel(float* __restrict__ agg,
                                 const float* __restrict__ bias) {
    int i4 = blockIdx.x * blockDim.x + threadIdx.x;
    const int C4 = C / 4;
    if (i4 >= N_NODES * C4) return;
    int c4 = i4 % C4;
    float4 v = ((float4*)agg)[i4];
    const float4 b = ((const float4*)bias)[c4];
    v.x = fmaxf(v.x + b.x, 0.f);
    v.y = fmaxf(v.y + b.y, 0.f);
    v.z = fmaxf(v.z + b.z, 0.f);
    v.w = fmaxf(v.w + b.w, 0.f);
    ((float4*)agg)[i4] = v;
}

// ---------------- launch ----------------------------------------------------
extern "C" void kernel_launch(void* const* d_in, const int* in_sizes, int n_in,
                              void* d_out, int out_size) {
    const float* x  = (const float*)d_in[0];
    const int*   ei = (const int*)d_in[1];     // int32: JAX x64 disabled
    const float* W1 = (const float*)d_in[2];
    const float* b1 = (const float*)d_in[3];
    const float* W2 = (const float*)d_in[4];
    const float* b2 = (const float*)d_in[5];
    float* out = (float*)d_out;

    const int* src = ei;
    const int* dst = ei + N_EDGES;

    float* g_h_p;    cudaGetSymbolAddress((void**)&g_h_p,    g_h);
    float* g_agg_p;  cudaGetSymbolAddress((void**)&g_agg_p,  g_agg);
    float* g_h2_p;   cudaGetSymbolAddress((void**)&g_h2_p,   g_h2);

    // 1) degrees -> dinv
    zero_deg_kernel<<<(N_NODES + 255) / 256, 256>>>();
    deg_count_kernel<<<(N_EDGES + 255) / 256, 256>>>(dst);
    deg_finalize_kernel<<<(N_NODES + 255) / 256, 256>>>();

    // 2) h = x @ W1
    {
        dim3 grid((N_NODES + 127) / 128, H1 / 128);
        sgemm128_kernel<<<grid, 256>>>(x, W1, g_h_p, N_NODES, H1, NFEAT);
    }

    // 3) agg = selfloop(h) ; scatter edges ; h1 = relu(agg + b1)
    {
        int n4 = N_NODES * (H1 / 4);
        init_selfloop_kernel<H1><<<(n4 + 255) / 256, 256>>>(g_h_p, g_agg_p, nullptr);
        scatter_kernel<H1><<<(N_EDGES * 32 + 255) / 256, 256>>>(src, dst, g_h_p, g_agg_p);
        bias_relu_kernel<H1><<<(n4 + 255) / 256, 256>>>(g_agg_p, b1);
    }

    // 4) h2 = h1 @ W2
    {
        dim3 grid((N_NODES + 127) / 128, H2 / 128);
        sgemm128_kernel<<<grid, 256>>>(g_agg_p, W2, g_h2_p, N_NODES, H2, H1);
    }

    // 5) out = selfloop(h2) + b2 ; scatter edges (bias folded into init)
    {
        int n4 = N_NODES * (H2 / 4);
        init_selfloop_kernel<H2><<<(n4 + 255) / 256, 256>>>(g_h2_p, out, b2);
        scatter_kernel<H2><<<(N_EDGES * 32 + 255) / 256, 256>>>(src, dst, g_h2_p, out);
    }
}

// round 5
// speedup vs baseline: 2.6201x; 1.6019x over previous
#include <cuda_runtime.h>
#include <cuda_bf16.h>
#include <cstdint>

#define N_NODES 50000
#define N_EDGES 800000
#define NFEAT   512
#define H1      256
#define H2      128

// ---------------- scratch (device globals; no allocation allowed) ----------
__device__ float g_dinv[N_NODES];              // degree -> deg^{-1/2}
__device__ float g_h  [N_NODES * H1];          // x @ W1
__device__ float g_agg[N_NODES * H1];          // layer-1 aggregation, then relu(h1)
__device__ float g_h2 [N_NODES * H2];          // h1 @ W2

// ---------------- helpers ---------------------------------------------------
__device__ __forceinline__ void red_add_v4(float* p, float4 v) {
    asm volatile("red.global.add.v4.f32 [%0], {%1, %2, %3, %4};"
                 :: "l"(p), "f"(v.x), "f"(v.y), "f"(v.z), "f"(v.w)
                 : "memory");
}
__device__ __forceinline__ float tf32r(float x) {
    float y; asm("cvt.rna.tf32.f32 %0, %1;" : "=f"(y) : "f"(x)); return y;
}
__device__ __forceinline__ void mma_tf32(float c[4], const uint32_t a[4],
                                         const uint32_t b[2]) {
    asm volatile(
        "mma.sync.aligned.m16n8k8.row.col.f32.tf32.tf32.f32 "
        "{%0,%1,%2,%3}, {%4,%5,%6,%7}, {%8,%9}, {%0,%1,%2,%3};"
        : "+f"(c[0]), "+f"(c[1]), "+f"(c[2]), "+f"(c[3])
        : "r"(a[0]), "r"(a[1]), "r"(a[2]), "r"(a[3]), "r"(b[0]), "r"(b[1]));
}

// ---------------- degree pipeline ------------------------------------------
__global__ void zero_deg_kernel() {
    int i = blockIdx.x * blockDim.x + threadIdx.x;
    if (i < N_NODES) g_dinv[i] = 0.0f;
}

__global__ void deg_count_kernel(const int* __restrict__ dst) {
    int e = blockIdx.x * blockDim.x + threadIdx.x;
    if (e < N_EDGES) atomicAdd(&g_dinv[dst[e]], 1.0f);
}

__global__ void deg_finalize_kernel() {
    int i = blockIdx.x * blockDim.x + threadIdx.x;
    if (i < N_NODES) {
        float d = g_dinv[i] + 1.0f;            // +1 self-loop
        g_dinv[i] = rsqrtf(d);                 // d >= 1 always
    }
}

// ---------------- tf32 tensor GEMM: C[M,N] = A[M,K] @ B[K,N] ----------------
// BM=128, BN=128, BK=32; 8 warps, warp tile 64x32 (m x n).
// Fused epilogue: C written; if agg != nullptr, agg = C * dinv[m]^2 (+bias).
__global__ __launch_bounds__(256, 2)
void tf32_gemm_kernel(const float* __restrict__ A, const float* __restrict__ B,
                      float* __restrict__ C, float* __restrict__ agg,
                      const float* __restrict__ bias,
                      int M, int N, int K) {
    __shared__ float As[128][36];   // [m][k], pad 36 -> conflict-free frag loads
    __shared__ float Bs[32][132];   // [k][n], pad 132

    int tid  = threadIdx.x;
    int m0   = blockIdx.x * 128;
    int n0   = blockIdx.y * 128;
    int wid  = tid >> 5;
    int lane = tid & 31;
    int wm = (wid & 1) * 64;        // warp m offset (2 warps in m)
    int wn = (wid >> 1) * 32;       // warp n offset (4 warps in n)
    int lq = lane >> 2;             // lane / 4
    int lr = lane & 3;              // lane % 4

    float c[4][4][4];               // [m16 tile][n8 tile][reg]
#pragma unroll
    for (int i = 0; i < 4; i++)
#pragma unroll
        for (int j = 0; j < 4; j++)
#pragma unroll
            for (int r = 0; r < 4; r++) c[i][j][r] = 0.0f;

    // tile loader indices
    int a_r = tid >> 3;             // 0..31 (step 32)
    int a_c = (tid & 7) * 4;        // 0..28
    int b_r = tid >> 5;             // 0..7  (step 8)
    int b_c = (tid & 31) * 4;       // 0..124

    for (int k0 = 0; k0 < K; k0 += 32) {
        // load + convert A tile (128 x 32)
#pragma unroll
        for (int p = 0; p < 4; p++) {
            int r = a_r + p * 32;
            float4 v = make_float4(0.f, 0.f, 0.f, 0.f);
            if (m0 + r < M)
                v = *(const float4*)(A + (size_t)(m0 + r) * K + k0 + a_c);
            As[r][a_c + 0] = tf32r(v.x);
            As[r][a_c + 1] = tf32r(v.y);
            As[r][a_c + 2] = tf32r(v.z);
            As[r][a_c + 3] = tf32r(v.w);
        }
        // load + convert B tile (32 x 128)
#pragma unroll
        for (int p = 0; p < 4; p++) {
            int r = b_r + p * 8;
            float4 v = *(const float4*)(B + (size_t)(k0 + r) * N + n0 + b_c);
            Bs[r][b_c + 0] = tf32r(v.x);
            Bs[r][b_c + 1] = tf32r(v.y);
            Bs[r][b_c + 2] = tf32r(v.z);
            Bs[r][b_c + 3] = tf32r(v.w);
        }
        __syncthreads();

#pragma unroll
        for (int kk = 0; kk < 4; kk++) {
            int k = kk * 8;
            uint32_t a[4][4], b[4][2];
#pragma unroll
            for (int i = 0; i < 4; i++) {
                int r = wm + i * 16 + lq;
                a[i][0] = __float_as_uint(As[r    ][k + lr    ]);
                a[i][1] = __float_as_uint(As[r + 8][k + lr    ]);
                a[i][2] = __float_as_uint(As[r    ][k + lr + 4]);
                a[i][3] = __float_as_uint(As[r + 8][k + lr + 4]);
            }
#pragma unroll
            for (int j = 0; j < 4; j++) {
                int cc = wn + j * 8 + lq;
                b[j][0] = __float_as_uint(Bs[k + lr    ][cc]);
                b[j][1] = __float_as_uint(Bs[k + lr + 4][cc]);
            }
#pragma unroll
            for (int i = 0; i < 4; i++)
#pragma unroll
                for (int j = 0; j < 4; j++)
                    mma_tf32(c[i][j], a[i], b[j]);
        }
        __syncthreads();
    }

    // epilogue
#pragma unroll
    for (int i = 0; i < 4; i++) {
        int r0 = m0 + wm + i * 16 + lq;
        int r1 = r0 + 8;
        bool v0 = r0 < M, v1 = r1 < M;
        float w0 = 0.f, w1 = 0.f;
        if (agg) {
            if (v0) { float d = g_dinv[r0]; w0 = d * d; }
            if (v1) { float d = g_dinv[r1]; w1 = d * d; }
        }
#pragma unroll
        for (int j = 0; j < 4; j++) {
            int col = n0 + wn + j * 8 + 2 * lr;
            if (v0) {
                float2 v = make_float2(c[i][j][0], c[i][j][1]);
                *(float2*)(C + (size_t)r0 * N + col) = v;
                if (agg) {
                    float2 o = make_float2(v.x * w0, v.y * w0);
                    if (bias) { o.x += bias[col]; o.y += bias[col + 1]; }
                    *(float2*)(agg + (size_t)r0 * N + col) = o;
                }
            }
            if (v1) {
                float2 v = make_float2(c[i][j][2], c[i][j][3]);
                *(float2*)(C + (size_t)r1 * N + col) = v;
                if (agg) {
                    float2 o = make_float2(v.x * w1, v.y * w1);
                    if (bias) { o.x += bias[col]; o.y += bias[col + 1]; }
                    *(float2*)(agg + (size_t)r1 * N + col) = o;
                }
            }
        }
    }
}

// ---------------- edge scatter: agg[dst] += h[src] * dinv[src]*dinv[dst] ----
template <int C>
__global__ void scatter_kernel(const int* __restrict__ src,
                               const int* __restrict__ dst,
                               const float* __restrict__ h,
                               float* __restrict__ agg) {
    int gw = (blockIdx.x * blockDim.x + threadIdx.x) >> 5;   // warp per edge
    int lane = threadIdx.x & 31;
    if (gw >= N_EDGES) return;
    int s = src[gw];
    int d = dst[gw];
    float norm = g_dinv[s] * g_dinv[d];
    const float4* hp = (const float4*)(h + (size_t)s * C);
    float4* ap = (float4*)(agg + (size_t)d * C);
    const int C4 = C / 4;
#pragma unroll
    for (int i = lane; i < C4; i += 32) {
        float4 v = hp[i];
        v.x *= norm; v.y *= norm; v.z *= norm; v.w *= norm;
        red_add_v4((float*)(ap + i), v);
    }
}

// ---------------- bias + relu (layer 1 epilogue) ----------------------------
template <int C>
__global__ void bias_relu_kernel(float* __restrict__ agg,
                                 const float* __restrict__ bias) {
    int i4 = blockIdx.x * blockDim.x + threadIdx.x;
    const int C4 = C / 4;
    if (i4 >= N_NODES * C4) return;
    int c4 = i4 % C4;
    float4 v = ((float4*)agg)[i4];
    const float4 b = ((const float4*)bias)[c4];
    v.x = fmaxf(v.x + b.x, 0.f);
    v.y = fmaxf(v.y + b.y, 0.f);
    v.z = fmaxf(v.z + b.z, 0.f);
    v.w = fmaxf(v.w + b.w, 0.f);
    ((float4*)agg)[i4] = v;
}

// ---------------- launch ----------------------------------------------------
extern "C" void kernel_launch(void* const* d_in, const int* in_sizes, int n_in,
                              void* d_out, int out_size) {
    const float* x  = (const float*)d_in[0];
    const int*   ei = (const int*)d_in[1];     // int32: JAX x64 disabled
    const float* W1 = (const float*)d_in[2];
    const float* b1 = (const float*)d_in[3];
    const float* W2 = (const float*)d_in[4];
    const float* b2 = (const float*)d_in[5];
    float* out = (float*)d_out;

    const int* src = ei;
    const int* dst = ei + N_EDGES;

    float* g_h_p;    cudaGetSymbolAddress((void**)&g_h_p,    g_h);
    float* g_agg_p;  cudaGetSymbolAddress((void**)&g_agg_p,  g_agg);
    float* g_h2_p;   cudaGetSymbolAddress((void**)&g_h2_p,   g_h2);

    // 1) degrees -> dinv
    zero_deg_kernel<<<(N_NODES + 255) / 256, 256>>>();
    deg_count_kernel<<<(N_EDGES + 255) / 256, 256>>>(dst);
    deg_finalize_kernel<<<(N_NODES + 255) / 256, 256>>>();

    // 2) h = x @ W1 ; agg = h * dinv^2 (self-loop init fused)
    {
        dim3 grid((N_NODES + 127) / 128, H1 / 128);
        tf32_gemm_kernel<<<grid, 256>>>(x, W1, g_h_p, g_agg_p, nullptr,
                                        N_NODES, H1, NFEAT);
    }

    // 3) scatter edges ; h1 = relu(agg + b1)
    {
        scatter_kernel<H1><<<(N_EDGES * 32 + 255) / 256, 256>>>(src, dst, g_h_p, g_agg_p);
        int n4 = N_NODES * (H1 / 4);
        bias_relu_kernel<H1><<<(n4 + 255) / 256, 256>>>(g_agg_p, b1);
    }

    // 4) h2 = h1 @ W2 ; out = h2 * dinv^2 + b2 (self-loop init + bias fused)
    {
        dim3 grid((N_NODES + 127) / 128, H2 / 128);
        tf32_gemm_kernel<<<grid, 256>>>(g_agg_p, W2, g_h2_p, out, b2,
                                        N_NODES, H2, H1);
    }

    // 5) scatter edges into out
    scatter_kernel<H2><<<(N_EDGES * 32 + 255) / 256, 256>>>(src, dst, g_h2_p, out);
}

// round 6
// speedup vs baseline: 3.1447x; 1.2002x over previous
#include <cuda_runtime.h>
#include <cuda_bf16.h>
#include <cstdint>

#define N_NODES 50000
#define N_EDGES 800000
#define NFEAT   512
#define H1      256
#define H2      128
#define SCAN_T  1024

// ---------------- scratch (device globals; no allocation allowed) ----------
__device__ float g_dinv[N_NODES];          // deg^{-1/2}
__device__ int   g_cnt [N_NODES];          // in-degree (real edges)
__device__ int   g_off [N_NODES];          // CSR row offsets
__device__ int   g_cur [N_NODES];          // fill cursors
__device__ int   g_csr_src[N_EDGES];       // src ids grouped by dst
__device__ float g_h  [N_NODES * H1];      // x @ W1
__device__ float g_agg[N_NODES * H1];      // relu(aggregate) = layer-2 input
__device__ float g_h2 [N_NODES * H2];      // h1 @ W2

// ---------------- helpers ---------------------------------------------------
__device__ __forceinline__ float tf32r(float x) {
    float y; asm("cvt.rna.tf32.f32 %0, %1;" : "=f"(y) : "f"(x)); return y;
}
__device__ __forceinline__ void mma_tf32(float c[4], const uint32_t a[4],
                                         const uint32_t b[2]) {
    asm volatile(
        "mma.sync.aligned.m16n8k8.row.col.f32.tf32.tf32.f32 "
        "{%0,%1,%2,%3}, {%4,%5,%6,%7}, {%8,%9}, {%0,%1,%2,%3};"
        : "+f"(c[0]), "+f"(c[1]), "+f"(c[2]), "+f"(c[3])
        : "r"(a[0]), "r"(a[1]), "r"(a[2]), "r"(a[3]), "r"(b[0]), "r"(b[1]));
}

// ---------------- CSR build --------------------------------------------------
__global__ void zero_cnt_kernel() {
    int i = blockIdx.x * blockDim.x + threadIdx.x;
    if (i < N_NODES) g_cnt[i] = 0;
}

__global__ void deg_count_kernel(const int* __restrict__ dst) {
    int e = blockIdx.x * blockDim.x + threadIdx.x;
    if (e < N_EDGES) atomicAdd(&g_cnt[dst[e]], 1);
}

__global__ void deg_finalize_kernel() {
    int i = blockIdx.x * blockDim.x + threadIdx.x;
    if (i < N_NODES) g_dinv[i] = rsqrtf((float)g_cnt[i] + 1.0f);  // +1 self-loop
}

// exclusive scan of g_cnt -> g_off (and g_cur), single block
__global__ __launch_bounds__(SCAN_T)
void scan_kernel() {
    __shared__ int sh[SCAN_T];
    int t = threadIdx.x;
    const int chunk = (N_NODES + SCAN_T - 1) / SCAN_T;
    int base = t * chunk;
    int s = 0;
#pragma unroll 4
    for (int i = 0; i < chunk; i++) {
        int idx = base + i;
        if (idx < N_NODES) s += g_cnt[idx];
    }
    sh[t] = s;
    __syncthreads();
    // Kogge-Stone inclusive scan over 1024 partials
    for (int d = 1; d < SCAN_T; d <<= 1) {
        int v = (t >= d) ? sh[t - d] : 0;
        __syncthreads();
        sh[t] += v;
        __syncthreads();
    }
    int run = sh[t] - s;   // exclusive prefix of this thread's chunk
    for (int i = 0; i < chunk; i++) {
        int idx = base + i;
        if (idx < N_NODES) {
            g_off[idx] = run;
            g_cur[idx] = run;
            run += g_cnt[idx];
        }
    }
}

__global__ void fill_kernel(const int* __restrict__ src,
                            const int* __restrict__ dst) {
    int e = blockIdx.x * blockDim.x + threadIdx.x;
    if (e >= N_EDGES) return;
    int pos = atomicAdd(&g_cur[dst[e]], 1);
    g_csr_src[pos] = src[e];
}

// ---------------- tf32 tensor GEMM: C[M,N] = A[M,K] @ B[K,N] ----------------
__global__ __launch_bounds__(256, 2)
void tf32_gemm_kernel(const float* __restrict__ A, const float* __restrict__ B,
                      float* __restrict__ C, int M, int N, int K) {
    __shared__ float As[128][36];
    __shared__ float Bs[32][132];

    int tid  = threadIdx.x;
    int m0   = blockIdx.x * 128;
    int n0   = blockIdx.y * 128;
    int wid  = tid >> 5;
    int lane = tid & 31;
    int wm = (wid & 1) * 64;
    int wn = (wid >> 1) * 32;
    int lq = lane >> 2;
    int lr = lane & 3;

    float c[4][4][4];
#pragma unroll
    for (int i = 0; i < 4; i++)
#pragma unroll
        for (int j = 0; j < 4; j++)
#pragma unroll
            for (int r = 0; r < 4; r++) c[i][j][r] = 0.0f;

    int a_r = tid >> 3;
    int a_c = (tid & 7) * 4;
    int b_r = tid >> 5;
    int b_c = (tid & 31) * 4;

    for (int k0 = 0; k0 < K; k0 += 32) {
#pragma unroll
        for (int p = 0; p < 4; p++) {
            int r = a_r + p * 32;
            float4 v = make_float4(0.f, 0.f, 0.f, 0.f);
            if (m0 + r < M)
                v = *(const float4*)(A + (size_t)(m0 + r) * K + k0 + a_c);
            As[r][a_c + 0] = tf32r(v.x);
            As[r][a_c + 1] = tf32r(v.y);
            As[r][a_c + 2] = tf32r(v.z);
            As[r][a_c + 3] = tf32r(v.w);
        }
#pragma unroll
        for (int p = 0; p < 4; p++) {
            int r = b_r + p * 8;
            float4 v = *(const float4*)(B + (size_t)(k0 + r) * N + n0 + b_c);
            Bs[r][b_c + 0] = tf32r(v.x);
            Bs[r][b_c + 1] = tf32r(v.y);
            Bs[r][b_c + 2] = tf32r(v.z);
            Bs[r][b_c + 3] = tf32r(v.w);
        }
        __syncthreads();

#pragma unroll
        for (int kk = 0; kk < 4; kk++) {
            int k = kk * 8;
            uint32_t a[4][4], b[4][2];
#pragma unroll
            for (int i = 0; i < 4; i++) {
                int r = wm + i * 16 + lq;
                a[i][0] = __float_as_uint(As[r    ][k + lr    ]);
                a[i][1] = __float_as_uint(As[r + 8][k + lr    ]);
                a[i][2] = __float_as_uint(As[r    ][k + lr + 4]);
                a[i][3] = __float_as_uint(As[r + 8][k + lr + 4]);
            }
#pragma unroll
            for (int j = 0; j < 4; j++) {
                int cc = wn + j * 8 + lq;
                b[j][0] = __float_as_uint(Bs[k + lr    ][cc]);
                b[j][1] = __float_as_uint(Bs[k + lr + 4][cc]);
            }
#pragma unroll
            for (int i = 0; i < 4; i++)
#pragma unroll
                for (int j = 0; j < 4; j++)
                    mma_tf32(c[i][j], a[i], b[j]);
        }
        __syncthreads();
    }

#pragma unroll
    for (int i = 0; i < 4; i++) {
        int r0 = m0 + wm + i * 16 + lq;
        int r1 = r0 + 8;
#pragma unroll
        for (int j = 0; j < 4; j++) {
            int col = n0 + wn + j * 8 + 2 * lr;
            if (r0 < M)
                *(float2*)(C + (size_t)r0 * N + col) =
                    make_float2(c[i][j][0], c[i][j][1]);
            if (r1 < M)
                *(float2*)(C + (size_t)r1 * N + col) =
                    make_float2(c[i][j][2], c[i][j][3]);
        }
    }
}

// ---------------- CSR gather: out[d] = f(dinv[d]^2 h[d] + sum norm h[s] + b) -
// warp per dst node; C channels held in registers (C/128 float4 per lane)
template <int C, bool RELU>
__global__ void gather_kernel(const float* __restrict__ h,
                              float* __restrict__ outp,
                              const float* __restrict__ bias) {
    int node = (blockIdx.x * blockDim.x + threadIdx.x) >> 5;
    int lane = threadIdx.x & 31;
    if (node >= N_NODES) return;
    const int CV = C / 128;            // float4 per lane

    float dd = g_dinv[node];
    float w  = dd * dd;

    float4 acc[CV];
    const float4* hd = (const float4*)(h + (size_t)node * C);
#pragma unroll
    for (int v = 0; v < CV; v++) {
        float4 t = hd[lane + 32 * v];
        acc[v] = make_float4(t.x * w, t.y * w, t.z * w, t.w * w);
    }

    int j   = g_off[node];
    int end = j + g_cnt[node];

    // unroll-by-2 for memory-level parallelism
    for (; j + 1 < end; j += 2) {
        int s0 = g_csr_src[j];
        int s1 = g_csr_src[j + 1];
        float n0 = g_dinv[s0] * dd;
        float n1 = g_dinv[s1] * dd;
        const float4* h0 = (const float4*)(h + (size_t)s0 * C);
        const float4* h1 = (const float4*)(h + (size_t)s1 * C);
#pragma unroll
        for (int v = 0; v < CV; v++) {
            float4 t0 = h0[lane + 32 * v];
            float4 t1 = h1[lane + 32 * v];
            acc[v].x += t0.x * n0; acc[v].y += t0.y * n0;
            acc[v].z += t0.z * n0; acc[v].w += t0.w * n0;
            acc[v].x += t1.x * n1; acc[v].y += t1.y * n1;
            acc[v].z += t1.z * n1; acc[v].w += t1.w * n1;
        }
    }
    if (j < end) {
        int s0 = g_csr_src[j];
        float n0 = g_dinv[s0] * dd;
        const float4* h0 = (const float4*)(h + (size_t)s0 * C);
#pragma unroll
        for (int v = 0; v < CV; v++) {
            float4 t0 = h0[lane + 32 * v];
            acc[v].x += t0.x * n0; acc[v].y += t0.y * n0;
            acc[v].z += t0.z * n0; acc[v].w += t0.w * n0;
        }
    }

    float4* op = (float4*)(outp + (size_t)node * C);
#pragma unroll
    for (int v = 0; v < CV; v++) {
        const float4 b = ((const float4*)bias)[lane + 32 * v];
        float4 o = acc[v];
        o.x += b.x; o.y += b.y; o.z += b.z; o.w += b.w;
        if (RELU) {
            o.x = fmaxf(o.x, 0.f); o.y = fmaxf(o.y, 0.f);
            o.z = fmaxf(o.z, 0.f); o.w = fmaxf(o.w, 0.f);
        }
        op[lane + 32 * v] = o;
    }
}

// ---------------- launch ----------------------------------------------------
extern "C" void kernel_launch(void* const* d_in, const int* in_sizes, int n_in,
                              void* d_out, int out_size) {
    const float* x  = (const float*)d_in[0];
    const int*   ei = (const int*)d_in[1];     // int32: JAX x64 disabled
    const float* W1 = (const float*)d_in[2];
    const float* b1 = (const float*)d_in[3];
    const float* W2 = (const float*)d_in[4];
    const float* b2 = (const float*)d_in[5];
    float* out = (float*)d_out;

    const int* src = ei;
    const int* dst = ei + N_EDGES;

    float* g_h_p;   cudaGetSymbolAddress((void**)&g_h_p,   g_h);
    float* g_agg_p; cudaGetSymbolAddress((void**)&g_agg_p, g_agg);
    float* g_h2_p;  cudaGetSymbolAddress((void**)&g_h2_p,  g_h2);

    // 1) CSR build + dinv
    zero_cnt_kernel<<<(N_NODES + 255) / 256, 256>>>();
    deg_count_kernel<<<(N_EDGES + 255) / 256, 256>>>(dst);
    deg_finalize_kernel<<<(N_NODES + 255) / 256, 256>>>();
    scan_kernel<<<1, SCAN_T>>>();
    fill_kernel<<<(N_EDGES + 255) / 256, 256>>>(src, dst);

    // 2) h = x @ W1
    {
        dim3 grid((N_NODES + 127) / 128, H1 / 128);
        tf32_gemm_kernel<<<grid, 256>>>(x, W1, g_h_p, N_NODES, H1, NFEAT);
    }

    // 3) h1 = relu(aggregate(h) + b1)   (self-loop + edges + bias + relu fused)
    gather_kernel<H1, true><<<(N_NODES * 32 + 255) / 256, 256>>>(g_h_p, g_agg_p, b1);

    // 4) h2 = h1 @ W2
    {
        dim3 grid((N_NODES + 127) / 128, H2 / 128);
        tf32_gemm_kernel<<<grid, 256>>>(g_agg_p, W2, g_h2_p, N_NODES, H2, H1);
    }

    // 5) out = aggregate(h2) + b2
    gather_kernel<H2, false><<<(N_NODES * 32 + 255) / 256, 256>>>(g_h2_p, out, b2);
}

// round 7
// speedup vs baseline: 3.8642x; 1.2288x over previous
#include <cuda_runtime.h>
#include <cuda_bf16.h>
#include <cstdint>

#define N_NODES 50000
#define N_EDGES 800000
#define NFEAT   512
#define H1      256
#define H2      128
#define SCAN_B  256
#define SCAN_NBLK ((N_NODES + SCAN_B - 1) / SCAN_B)   // 196

// ---------------- scratch (device globals; no allocation allowed) ----------
__device__ float g_dinv[N_NODES];          // deg^{-1/2}
__device__ int   g_cnt [N_NODES];          // in-degree (real edges)
__device__ int   g_off [N_NODES];          // CSR row offsets
__device__ int   g_cur [N_NODES];          // fill cursors
__device__ int   g_csr_src[N_EDGES];       // src ids grouped by dst
__device__ int   g_blksum[SCAN_NBLK];      // per-block sums for scan
__device__ float g_h  [N_NODES * H1];      // x @ W1
__device__ float g_agg[N_NODES * H1];      // relu(aggregate) = layer-2 input
__device__ float g_h2 [N_NODES * H2];      // h1 @ W2

// ---------------- helpers ---------------------------------------------------
__device__ __forceinline__ float tf32r(float x) {
    float y; asm("cvt.rna.tf32.f32 %0, %1;" : "=f"(y) : "f"(x)); return y;
}
__device__ __forceinline__ void mma_tf32(float c[4], const uint32_t a[4],
                                         const uint32_t b[2]) {
    asm volatile(
        "mma.sync.aligned.m16n8k8.row.col.f32.tf32.tf32.f32 "
        "{%0,%1,%2,%3}, {%4,%5,%6,%7}, {%8,%9}, {%0,%1,%2,%3};"
        : "+f"(c[0]), "+f"(c[1]), "+f"(c[2]), "+f"(c[3])
        : "r"(a[0]), "r"(a[1]), "r"(a[2]), "r"(a[3]), "r"(b[0]), "r"(b[1]));
}

// ---------------- CSR build --------------------------------------------------
__global__ void zero_cnt_kernel() {
    int i = blockIdx.x * blockDim.x + threadIdx.x;
    if (i < N_NODES) g_cnt[i] = 0;
}

__global__ void deg_count_kernel(const int* __restrict__ dst) {
    int e = blockIdx.x * blockDim.x + threadIdx.x;
    if (e < N_EDGES) atomicAdd(&g_cnt[dst[e]], 1);
}

__global__ void deg_finalize_kernel() {
    int i = blockIdx.x * blockDim.x + threadIdx.x;
    if (i < N_NODES) g_dinv[i] = rsqrtf((float)g_cnt[i] + 1.0f);  // +1 self-loop
}

// Phase A: per-block sums of g_cnt
__global__ __launch_bounds__(SCAN_B)
void scanA_kernel() {
    __shared__ int sh[SCAN_B / 32];
    int idx = blockIdx.x * SCAN_B + threadIdx.x;
    int v = (idx < N_NODES) ? g_cnt[idx] : 0;
#pragma unroll
    for (int d = 16; d > 0; d >>= 1) v += __shfl_down_sync(~0u, v, d);
    if ((threadIdx.x & 31) == 0) sh[threadIdx.x >> 5] = v;
    __syncthreads();
    if (threadIdx.x < SCAN_B / 32) {
        int s = sh[threadIdx.x];
#pragma unroll
        for (int d = SCAN_B / 64; d > 0; d >>= 1) s += __shfl_down_sync(~0u, s, d);
        if (threadIdx.x == 0) g_blksum[blockIdx.x] = s;
    }
}

// Phase B: exclusive scan of the 196 block sums (one block)
__global__ __launch_bounds__(SCAN_B)
void scanB_kernel() {
    __shared__ int sh[SCAN_B];
    int t = threadIdx.x;
    int v = (t < SCAN_NBLK) ? g_blksum[t] : 0;
    sh[t] = v;
    __syncthreads();
    for (int d = 1; d < SCAN_B; d <<= 1) {
        int u = (t >= d) ? sh[t - d] : 0;
        __syncthreads();
        sh[t] += u;
        __syncthreads();
    }
    if (t < SCAN_NBLK) g_blksum[t] = sh[t] - v;   // exclusive
}

// Phase C: local exclusive scan + block base -> g_off, g_cur
__global__ __launch_bounds__(SCAN_B)
void scanC_kernel() {
    __shared__ int sh[SCAN_B];
    int t = threadIdx.x;
    int idx = blockIdx.x * SCAN_B + t;
    int v = (idx < N_NODES) ? g_cnt[idx] : 0;
    sh[t] = v;
    __syncthreads();
    for (int d = 1; d < SCAN_B; d <<= 1) {
        int u = (t >= d) ? sh[t - d] : 0;
        __syncthreads();
        sh[t] += u;
        __syncthreads();
    }
    if (idx < N_NODES) {
        int off = g_blksum[blockIdx.x] + sh[t] - v;
        g_off[idx] = off;
        g_cur[idx] = off;
    }
}

__global__ void fill_kernel(const int* __restrict__ src,
                            const int* __restrict__ dst) {
    int e = blockIdx.x * blockDim.x + threadIdx.x;
    if (e >= N_EDGES) return;
    int pos = atomicAdd(&g_cur[dst[e]], 1);
    g_csr_src[pos] = src[e];
}

// ---------------- tf32 tensor GEMM: C[M,N] = A[M,K] @ B[K,N] ----------------
__global__ __launch_bounds__(256, 2)
void tf32_gemm_kernel(const float* __restrict__ A, const float* __restrict__ B,
                      float* __restrict__ C, int M, int N, int K) {
    __shared__ float As[128][36];
    __shared__ float Bs[32][132];

    int tid  = threadIdx.x;
    int m0   = blockIdx.x * 128;
    int n0   = blockIdx.y * 128;
    int wid  = tid >> 5;
    int lane = tid & 31;
    int wm = (wid & 1) * 64;
    int wn = (wid >> 1) * 32;
    int lq = lane >> 2;
    int lr = lane & 3;

    float c[4][4][4];
#pragma unroll
    for (int i = 0; i < 4; i++)
#pragma unroll
        for (int j = 0; j < 4; j++)
#pragma unroll
            for (int r = 0; r < 4; r++) c[i][j][r] = 0.0f;

    int a_r = tid >> 3;
    int a_c = (tid & 7) * 4;
    int b_r = tid >> 5;
    int b_c = (tid & 31) * 4;

    for (int k0 = 0; k0 < K; k0 += 32) {
#pragma unroll
        for (int p = 0; p < 4; p++) {
            int r = a_r + p * 32;
            float4 v = make_float4(0.f, 0.f, 0.f, 0.f);
            if (m0 + r < M)
                v = *(const float4*)(A + (size_t)(m0 + r) * K + k0 + a_c);
            As[r][a_c + 0] = tf32r(v.x);
            As[r][a_c + 1] = tf32r(v.y);
            As[r][a_c + 2] = tf32r(v.z);
            As[r][a_c + 3] = tf32r(v.w);
        }
#pragma unroll
        for (int p = 0; p < 4; p++) {
            int r = b_r + p * 8;
            float4 v = *(const float4*)(B + (size_t)(k0 + r) * N + n0 + b_c);
            Bs[r][b_c + 0] = tf32r(v.x);
            Bs[r][b_c + 1] = tf32r(v.y);
            Bs[r][b_c + 2] = tf32r(v.z);
            Bs[r][b_c + 3] = tf32r(v.w);
        }
        __syncthreads();

#pragma unroll
        for (int kk = 0; kk < 4; kk++) {
            int k = kk * 8;
            uint32_t a[4][4], b[4][2];
#pragma unroll
            for (int i = 0; i < 4; i++) {
                int r = wm + i * 16 + lq;
                a[i][0] = __float_as_uint(As[r    ][k + lr    ]);
                a[i][1] = __float_as_uint(As[r + 8][k + lr    ]);
                a[i][2] = __float_as_uint(As[r    ][k + lr + 4]);
                a[i][3] = __float_as_uint(As[r + 8][k + lr + 4]);
            }
#pragma unroll
            for (int j = 0; j < 4; j++) {
                int cc = wn + j * 8 + lq;
                b[j][0] = __float_as_uint(Bs[k + lr    ][cc]);
                b[j][1] = __float_as_uint(Bs[k + lr + 4][cc]);
            }
#pragma unroll
            for (int i = 0; i < 4; i++)
#pragma unroll
                for (int j = 0; j < 4; j++)
                    mma_tf32(c[i][j], a[i], b[j]);
        }
        __syncthreads();
    }

#pragma unroll
    for (int i = 0; i < 4; i++) {
        int r0 = m0 + wm + i * 16 + lq;
        int r1 = r0 + 8;
#pragma unroll
        for (int j = 0; j < 4; j++) {
            int col = n0 + wn + j * 8 + 2 * lr;
            if (r0 < M)
                *(float2*)(C + (size_t)r0 * N + col) =
                    make_float2(c[i][j][0], c[i][j][1]);
            if (r1 < M)
                *(float2*)(C + (size_t)r1 * N + col) =
                    make_float2(c[i][j][2], c[i][j][3]);
        }
    }
}

// ---------------- CSR gather: out[d] = f(dinv[d]^2 h[d] + sum norm h[s] + b) -
template <int C, bool RELU>
__global__ void gather_kernel(const float* __restrict__ h,
                              float* __restrict__ outp,
                              const float* __restrict__ bias) {
    int node = (blockIdx.x * blockDim.x + threadIdx.x) >> 5;
    int lane = threadIdx.x & 31;
    if (node >= N_NODES) return;
    const int CV = C / 128;            // float4 per lane

    float dd = g_dinv[node];
    float w  = dd * dd;

    float4 acc[CV];
    const float4* hd = (const float4*)(h + (size_t)node * C);
#pragma unroll
    for (int v = 0; v < CV; v++) {
        float4 t = hd[lane + 32 * v];
        acc[v] = make_float4(t.x * w, t.y * w, t.z * w, t.w * w);
    }

    int j   = g_off[node];
    int end = j + g_cnt[node];

    for (; j + 1 < end; j += 2) {
        int s0 = g_csr_src[j];
        int s1 = g_csr_src[j + 1];
        float n0 = g_dinv[s0] * dd;
        float n1 = g_dinv[s1] * dd;
        const float4* h0 = (const float4*)(h + (size_t)s0 * C);
        const float4* h1 = (const float4*)(h + (size_t)s1 * C);
#pragma unroll
        for (int v = 0; v < CV; v++) {
            float4 t0 = h0[lane + 32 * v];
            float4 t1 = h1[lane + 32 * v];
            acc[v].x += t0.x * n0; acc[v].y += t0.y * n0;
            acc[v].z += t0.z * n0; acc[v].w += t0.w * n0;
            acc[v].x += t1.x * n1; acc[v].y += t1.y * n1;
            acc[v].z += t1.z * n1; acc[v].w += t1.w * n1;
        }
    }
    if (j < end) {
        int s0 = g_csr_src[j];
        float n0 = g_dinv[s0] * dd;
        const float4* h0 = (const float4*)(h + (size_t)s0 * C);
#pragma unroll
        for (int v = 0; v < CV; v++) {
            float4 t0 = h0[lane + 32 * v];
            acc[v].x += t0.x * n0; acc[v].y += t0.y * n0;
            acc[v].z += t0.z * n0; acc[v].w += t0.w * n0;
        }
    }

    float4* op = (float4*)(outp + (size_t)node * C);
#pragma unroll
    for (int v = 0; v < CV; v++) {
        const float4 b = ((const float4*)bias)[lane + 32 * v];
        float4 o = acc[v];
        o.x += b.x; o.y += b.y; o.z += b.z; o.w += b.w;
        if (RELU) {
            o.x = fmaxf(o.x, 0.f); o.y = fmaxf(o.y, 0.f);
            o.z = fmaxf(o.z, 0.f); o.w = fmaxf(o.w, 0.f);
        }
        op[lane + 32 * v] = o;
    }
}

// ---------------- launch ----------------------------------------------------
extern "C" void kernel_launch(void* const* d_in, const int* in_sizes, int n_in,
                              void* d_out, int out_size) {
    const float* x  = (const float*)d_in[0];
    const int*   ei = (const int*)d_in[1];     // int32: JAX x64 disabled
    const float* W1 = (const float*)d_in[2];
    const float* b1 = (const float*)d_in[3];
    const float* W2 = (const float*)d_in[4];
    const float* b2 = (const float*)d_in[5];
    float* out = (float*)d_out;

    const int* src = ei;
    const int* dst = ei + N_EDGES;

    float* g_h_p;   cudaGetSymbolAddress((void**)&g_h_p,   g_h);
    float* g_agg_p; cudaGetSymbolAddress((void**)&g_agg_p, g_agg);
    float* g_h2_p;  cudaGetSymbolAddress((void**)&g_h2_p,  g_h2);

    // 1) CSR build + dinv
    zero_cnt_kernel<<<(N_NODES + 255) / 256, 256>>>();
    deg_count_kernel<<<(N_EDGES + 255) / 256, 256>>>(dst);
    deg_finalize_kernel<<<(N_NODES + 255) / 256, 256>>>();
    scanA_kernel<<<SCAN_NBLK, SCAN_B>>>();
    scanB_kernel<<<1, SCAN_B>>>();
    scanC_kernel<<<SCAN_NBLK, SCAN_B>>>();
    fill_kernel<<<(N_EDGES + 255) / 256, 256>>>(src, dst);

    // 2) h = x @ W1
    {
        dim3 grid((N_NODES + 127) / 128, H1 / 128);
        tf32_gemm_kernel<<<grid, 256>>>(x, W1, g_h_p, N_NODES, H1, NFEAT);
    }

    // 3) h1 = relu(aggregate(h) + b1)
    gather_kernel<H1, true><<<(N_NODES * 32 + 255) / 256, 256>>>(g_h_p, g_agg_p, b1);

    // 4) h2 = h1 @ W2
    {
        dim3 grid((N_NODES + 127) / 128, H2 / 128);
        tf32_gemm_kernel<<<grid, 256>>>(g_agg_p, W2, g_h2_p, N_NODES, H2, H1);
    }

    // 5) out = aggregate(h2) + b2
    gather_kernel<H2, false><<<(N_NODES * 32 + 255) / 256, 256>>>(g_h2_p, out, b2);
}

// round 9
// speedup vs baseline: 4.5918x; 1.1883x over previous
#include <cuda_runtime.h>
#include <cuda_bf16.h>
#include <cstdint>

#define N_NODES 50000
#define N_EDGES 800000
#define NFEAT   512
#define H1      256
#define H2      128
#define SCAN_B  256
#define SCAN_NBLK ((N_NODES + SCAN_B - 1) / SCAN_B)   // 196

// ---------------- scratch (device globals; no allocation allowed) ----------
__device__ float g_dinv[N_NODES];          // deg^{-1/2}
__device__ int   g_cnt [N_NODES];          // in-degree (real edges)
__device__ int   g_off [N_NODES];          // CSR row offsets
__device__ int   g_cur [N_NODES];          // fill cursors
__device__ int   g_csr_src[N_EDGES];       // src ids grouped by dst
__device__ int   g_blksum[SCAN_NBLK];      // per-block sums for scan
__device__ float g_h  [N_NODES * H1];      // x @ W1
__device__ float g_agg[N_NODES * H1];      // relu(aggregate) = layer-2 input
__device__ float g_h2 [N_NODES * H2];      // h1 @ W2

// ---------------- helpers ---------------------------------------------------
__device__ __forceinline__ uint32_t tf32u(float x) {
    float y; asm("cvt.rna.tf32.f32 %0, %1;" : "=f"(y) : "f"(x));
    return __float_as_uint(y);
}
__device__ __forceinline__ void mma_tf32(float c[4], const uint32_t a[4],
                                         const uint32_t b[2]) {
    asm volatile(
        "mma.sync.aligned.m16n8k8.row.col.f32.tf32.tf32.f32 "
        "{%0,%1,%2,%3}, {%4,%5,%6,%7}, {%8,%9}, {%0,%1,%2,%3};"
        : "+f"(c[0]), "+f"(c[1]), "+f"(c[2]), "+f"(c[3])
        : "r"(a[0]), "r"(a[1]), "r"(a[2]), "r"(a[3]), "r"(b[0]), "r"(b[1]));
}
__device__ __forceinline__ void cp_async16(void* smem, const void* gmem, bool valid) {
    uint32_t s = (uint32_t)__cvta_generic_to_shared(smem);
    int sz = valid ? 16 : 0;
    asm volatile("cp.async.cg.shared.global [%0], [%1], 16, %2;"
                 :: "r"(s), "l"(gmem), "r"(sz));
}
#define CP_COMMIT() asm volatile("cp.async.commit_group;")
#define CP_WAIT1()  asm volatile("cp.async.wait_group 1;")
#define CP_WAIT0()  asm volatile("cp.async.wait_group 0;")

// ---------------- CSR build --------------------------------------------------
__global__ void zero_cnt_kernel() {
    int i = blockIdx.x * blockDim.x + threadIdx.x;
    if (i < N_NODES) g_cnt[i] = 0;
}

__global__ void deg_count_kernel(const int* __restrict__ dst) {
    int e = blockIdx.x * blockDim.x + threadIdx.x;
    if (e < N_EDGES) atomicAdd(&g_cnt[dst[e]], 1);
}

__global__ void deg_finalize_kernel() {
    int i = blockIdx.x * blockDim.x + threadIdx.x;
    if (i < N_NODES) g_dinv[i] = rsqrtf((float)g_cnt[i] + 1.0f);  // +1 self-loop
}

__global__ __launch_bounds__(SCAN_B)
void scanA_kernel() {
    __shared__ int sh[SCAN_B / 32];
    int idx = blockIdx.x * SCAN_B + threadIdx.x;
    int v = (idx < N_NODES) ? g_cnt[idx] : 0;
#pragma unroll
    for (int d = 16; d > 0; d >>= 1) v += __shfl_down_sync(~0u, v, d);
    if ((threadIdx.x & 31) == 0) sh[threadIdx.x >> 5] = v;
    __syncthreads();
    if (threadIdx.x < SCAN_B / 32) {
        int s = sh[threadIdx.x];
#pragma unroll
        for (int d = SCAN_B / 64; d > 0; d >>= 1) s += __shfl_down_sync(~0u, s, d);
        if (threadIdx.x == 0) g_blksum[blockIdx.x] = s;
    }
}

__global__ __launch_bounds__(SCAN_B)
void scanB_kernel() {
    __shared__ int sh[SCAN_B];
    int t = threadIdx.x;
    int v = (t < SCAN_NBLK) ? g_blksum[t] : 0;
    sh[t] = v;
    __syncthreads();
    for (int d = 1; d < SCAN_B; d <<= 1) {
        int u = (t >= d) ? sh[t - d] : 0;
        __syncthreads();
        sh[t] += u;
        __syncthreads();
    }
    if (t < SCAN_NBLK) g_blksum[t] = sh[t] - v;   // exclusive
}

__global__ __launch_bounds__(SCAN_B)
void scanC_kernel() {
    __shared__ int sh[SCAN_B];
    int t = threadIdx.x;
    int idx = blockIdx.x * SCAN_B + t;
    int v = (idx < N_NODES) ? g_cnt[idx] : 0;
    sh[t] = v;
    __syncthreads();
    for (int d = 1; d < SCAN_B; d <<= 1) {
        int u = (t >= d) ? sh[t - d] : 0;
        __syncthreads();
        sh[t] += u;
        __syncthreads();
    }
    if (idx < N_NODES) {
        int off = g_blksum[blockIdx.x] + sh[t] - v;
        g_off[idx] = off;
        g_cur[idx] = off;
    }
}

__global__ void fill_kernel(const int* __restrict__ src,
                            const int* __restrict__ dst) {
    int e = blockIdx.x * blockDim.x + threadIdx.x;
    if (e >= N_EDGES) return;
    int pos = atomicAdd(&g_cur[dst[e]], 1);
    g_csr_src[pos] = src[e];
}

// ---------------- tf32 tensor GEMM (cp.async 2-stage pipeline) --------------
// BM=128, BN=128, BK=32; 8 warps, warp tile 64x32.
// fp32 tiles in smem; cvt.rna.tf32 at fragment load (matches JAX rna rounding).
#define AS_LD 36
#define BS_LD 132
struct GemmSmem {
    float As[2][128][AS_LD];
    float Bs[2][32][BS_LD];
};

__global__ __launch_bounds__(256, 2)
void tf32_gemm_kernel(const float* __restrict__ A, const float* __restrict__ B,
                      float* __restrict__ C, int M, int N, int K) {
    extern __shared__ char smem_raw[];
    GemmSmem& sm = *reinterpret_cast<GemmSmem*>(smem_raw);

    int tid  = threadIdx.x;
    int m0   = blockIdx.x * 128;
    int n0   = blockIdx.y * 128;
    int wid  = tid >> 5;
    int lane = tid & 31;
    int wm = (wid & 1) * 64;
    int wn = (wid >> 1) * 32;
    int lq = lane >> 2;
    int lr = lane & 3;

    float c[4][4][4];
#pragma unroll
    for (int i = 0; i < 4; i++)
#pragma unroll
        for (int j = 0; j < 4; j++)
#pragma unroll
            for (int r = 0; r < 4; r++) c[i][j][r] = 0.0f;

    int a_r = tid >> 3;             // 0..31 (stride 32)
    int a_c = (tid & 7) * 4;        // 0..28
    int b_r = tid >> 5;             // 0..7  (stride 8)
    int b_c = (tid & 31) * 4;       // 0..124

    auto issue_tile = [&](int k0, int buf) {
#pragma unroll
        for (int p = 0; p < 4; p++) {
            int r = a_r + p * 32;
            bool valid = (m0 + r) < M;
            const float* gp = A + (size_t)(valid ? (m0 + r) : 0) * K + k0 + a_c;
            cp_async16(&sm.As[buf][r][a_c], gp, valid);
        }
#pragma unroll
        for (int p = 0; p < 4; p++) {
            int r = b_r + p * 8;
            cp_async16(&sm.Bs[buf][r][b_c], B + (size_t)(k0 + r) * N + n0 + b_c, true);
        }
    };

    const int nk = K / 32;
    issue_tile(0, 0);
    CP_COMMIT();

    for (int it = 0; it < nk; it++) {
        if (it + 1 < nk) {
            issue_tile((it + 1) * 32, (it + 1) & 1);
            CP_COMMIT();
            CP_WAIT1();
        } else {
            CP_WAIT0();
        }
        __syncthreads();

        int buf = it & 1;
#pragma unroll
        for (int kk = 0; kk < 4; kk++) {
            int k = kk * 8;
            uint32_t a[4][4], b[4][2];
#pragma unroll
            for (int i = 0; i < 4; i++) {
                int r = wm + i * 16 + lq;
                a[i][0] = tf32u(sm.As[buf][r    ][k + lr    ]);
                a[i][1] = tf32u(sm.As[buf][r + 8][k + lr    ]);
                a[i][2] = tf32u(sm.As[buf][r    ][k + lr + 4]);
                a[i][3] = tf32u(sm.As[buf][r + 8][k + lr + 4]);
            }
#pragma unroll
            for (int j = 0; j < 4; j++) {
                int cc = wn + j * 8 + lq;
                b[j][0] = tf32u(sm.Bs[buf][k + lr    ][cc]);
                b[j][1] = tf32u(sm.Bs[buf][k + lr + 4][cc]);
            }
#pragma unroll
            for (int i = 0; i < 4; i++)
#pragma unroll
                for (int j = 0; j < 4; j++)
                    mma_tf32(c[i][j], a[i], b[j]);
        }
        __syncthreads();
    }

#pragma unroll
    for (int i = 0; i < 4; i++) {
        int r0 = m0 + wm + i * 16 + lq;
        int r1 = r0 + 8;
#pragma unroll
        for (int j = 0; j < 4; j++) {
            int col = n0 + wn + j * 8 + 2 * lr;
            if (r0 < M)
                *(float2*)(C + (size_t)r0 * N + col) =
                    make_float2(c[i][j][0], c[i][j][1]);
            if (r1 < M)
                *(float2*)(C + (size_t)r1 * N + col) =
                    make_float2(c[i][j][2], c[i][j][3]);
        }
    }
}

// ---------------- CSR gather: out[d] = f(dinv[d]^2 h[d] + sum norm h[s] + b) -
template <int C, bool RELU>
__global__ void gather_kernel(const float* __restrict__ h,
                              float* __restrict__ outp,
                              const float* __restrict__ bias) {
    int node = (blockIdx.x * blockDim.x + threadIdx.x) >> 5;
    int lane = threadIdx.x & 31;
    if (node >= N_NODES) return;
    const int CV = C / 128;            // float4 per lane

    float dd = g_dinv[node];
    float w  = dd * dd;

    float4 acc[CV];
    const float4* hd = (const float4*)(h + (size_t)node * C);
#pragma unroll
    for (int v = 0; v < CV; v++) {
        float4 t = hd[lane + 32 * v];
        acc[v] = make_float4(t.x * w, t.y * w, t.z * w, t.w * w);
    }

    int j   = g_off[node];
    int end = j + g_cnt[node];

    // unroll-by-4 for memory-level parallelism
    for (; j + 3 < end; j += 4) {
        int s0 = g_csr_src[j],     s1 = g_csr_src[j + 1];
        int s2 = g_csr_src[j + 2], s3 = g_csr_src[j + 3];
        float n0 = g_dinv[s0] * dd, n1 = g_dinv[s1] * dd;
        float n2 = g_dinv[s2] * dd, n3 = g_dinv[s3] * dd;
        const float4* h0 = (const float4*)(h + (size_t)s0 * C);
        const float4* h1 = (const float4*)(h + (size_t)s1 * C);
        const float4* h2 = (const float4*)(h + (size_t)s2 * C);
        const float4* h3 = (const float4*)(h + (size_t)s3 * C);
#pragma unroll
        for (int v = 0; v < CV; v++) {
            float4 t0 = h0[lane + 32 * v];
            float4 t1 = h1[lane + 32 * v];
            float4 t2 = h2[lane + 32 * v];
            float4 t3 = h3[lane + 32 * v];
            acc[v].x += t0.x * n0; acc[v].y += t0.y * n0;
            acc[v].z += t0.z * n0; acc[v].w += t0.w * n0;
            acc[v].x += t1.x * n1; acc[v].y += t1.y * n1;
            acc[v].z += t1.z * n1; acc[v].w += t1.w * n1;
            acc[v].x += t2.x * n2; acc[v].y += t2.y * n2;
            acc[v].z += t2.z * n2; acc[v].w += t2.w * n2;
            acc[v].x += t3.x * n3; acc[v].y += t3.y * n3;
            acc[v].z += t3.z * n3; acc[v].w += t3.w * n3;
        }
    }
    for (; j < end; j++) {
        int s0 = g_csr_src[j];
        float n0 = g_dinv[s0] * dd;
        const float4* h0 = (const float4*)(h + (size_t)s0 * C);
#pragma unroll
        for (int v = 0; v < CV; v++) {
            float4 t0 = h0[lane + 32 * v];
            acc[v].x += t0.x * n0; acc[v].y += t0.y * n0;
            acc[v].z += t0.z * n0; acc[v].w += t0.w * n0;
        }
    }

    float4* op = (float4*)(outp + (size_t)node * C);
#pragma unroll
    for (int v = 0; v < CV; v++) {
        const float4 b = ((const float4*)bias)[lane + 32 * v];
        float4 o = acc[v];
        o.x += b.x; o.y += b.y; o.z += b.z; o.w += b.w;
        if (RELU) {
            o.x = fmaxf(o.x, 0.f); o.y = fmaxf(o.y, 0.f);
            o.z = fmaxf(o.z, 0.f); o.w = fmaxf(o.w, 0.f);
        }
        op[lane + 32 * v] = o;
    }
}

// ---------------- launch ----------------------------------------------------
extern "C" void kernel_launch(void* const* d_in, const int* in_sizes, int n_in,
                              void* d_out, int out_size) {
    const float* x  = (const float*)d_in[0];
    const int*   ei = (const int*)d_in[1];     // int32: JAX x64 disabled
    const float* W1 = (const float*)d_in[2];
    const float* b1 = (const float*)d_in[3];
    const float* W2 = (const float*)d_in[4];
    const float* b2 = (const float*)d_in[5];
    float* out = (float*)d_out;

    const int* src = ei;
    const int* dst = ei + N_EDGES;

    float* g_h_p;   cudaGetSymbolAddress((void**)&g_h_p,   g_h);
    float* g_agg_p; cudaGetSymbolAddress((void**)&g_agg_p, g_agg);
    float* g_h2_p;  cudaGetSymbolAddress((void**)&g_h2_p,  g_h2);

    const int gemm_smem = sizeof(GemmSmem);           // ~69 KB
    static bool attr_set = false;
    if (!attr_set) {
        cudaFuncSetAttribute(tf32_gemm_kernel,
                             cudaFuncAttributeMaxDynamicSharedMemorySize, gemm_smem);
        attr_set = true;
    }

    // 1) CSR build + dinv
    zero_cnt_kernel<<<(N_NODES + 255) / 256, 256>>>();
    deg_count_kernel<<<(N_EDGES + 255) / 256, 256>>>(dst);
    deg_finalize_kernel<<<(N_NODES + 255) / 256, 256>>>();
    scanA_kernel<<<SCAN_NBLK, SCAN_B>>>();
    scanB_kernel<<<1, SCAN_B>>>();
    scanC_kernel<<<SCAN_NBLK, SCAN_B>>>();
    fill_kernel<<<(N_EDGES + 255) / 256, 256>>>(src, dst);

    // 2) h = x @ W1
    {
        dim3 grid((N_NODES + 127) / 128, H1 / 128);
        tf32_gemm_kernel<<<grid, 256, gemm_smem>>>(x, W1, g_h_p, N_NODES, H1, NFEAT);
    }

    // 3) h1 = relu(aggregate(h) + b1)
    gather_kernel<H1, true><<<(N_NODES * 32 + 255) / 256, 256>>>(g_h_p, g_agg_p, b1);

    // 4) h2 = h1 @ W2
    {
        dim3 grid((N_NODES + 127) / 128, H2 / 128);
        tf32_gemm_kernel<<<grid, 256, gemm_smem>>>(g_agg_p, W2, g_h2_p, N_NODES, H2, H1);
    }

    // 5) out = aggregate(h2) + b2
    gather_kernel<H2, false><<<(N_NODES * 32 + 255) / 256, 256>>>(g_h2_p, out, b2);
}

// round 10
// speedup vs baseline: 4.8212x; 1.0500x over previous
#include <cuda_runtime.h>
#include <cuda_bf16.h>
#include <cstdint>

#define N_NODES 50000
#define N_EDGES 800000
#define NFEAT   512
#define H1      256
#define H2      128
#define SCAN_B  256
#define SCAN_NBLK ((N_NODES + SCAN_B - 1) / SCAN_B)   // 196

// ---------------- scratch (device globals; no allocation allowed) ----------
__device__ float g_dinv[N_NODES];          // deg^{-1/2}
__device__ int   g_cnt [N_NODES];          // in-degree (real edges)
__device__ int   g_off [N_NODES];          // CSR row offsets
__device__ int   g_cur [N_NODES];          // fill cursors
__device__ int   g_csr_src[N_EDGES];       // src ids grouped by dst
__device__ int   g_blksum[SCAN_NBLK];      // per-block sums for scan
__device__ __nv_bfloat16 g_h  [N_NODES * H1];   // x @ W1 (bf16)
__device__ float         g_agg[N_NODES * H1];   // relu(aggregate), layer-2 input
__device__ __nv_bfloat16 g_h2 [N_NODES * H2];   // h1 @ W2 (bf16)

// ---------------- helpers ---------------------------------------------------
__device__ __forceinline__ uint32_t tf32u(float x) {
    float y; asm("cvt.rna.tf32.f32 %0, %1;" : "=f"(y) : "f"(x));
    return __float_as_uint(y);
}
__device__ __forceinline__ void mma_tf32(float c[4], const uint32_t a[4],
                                         const uint32_t b[2]) {
    asm volatile(
        "mma.sync.aligned.m16n8k8.row.col.f32.tf32.tf32.f32 "
        "{%0,%1,%2,%3}, {%4,%5,%6,%7}, {%8,%9}, {%0,%1,%2,%3};"
        : "+f"(c[0]), "+f"(c[1]), "+f"(c[2]), "+f"(c[3])
        : "r"(a[0]), "r"(a[1]), "r"(a[2]), "r"(a[3]), "r"(b[0]), "r"(b[1]));
}
__device__ __forceinline__ void cp_async16(void* smem, const void* gmem, bool valid) {
    uint32_t s = (uint32_t)__cvta_generic_to_shared(smem);
    int sz = valid ? 16 : 0;
    asm volatile("cp.async.cg.shared.global [%0], [%1], 16, %2;"
                 :: "r"(s), "l"(gmem), "r"(sz));
}
#define CP_COMMIT() asm volatile("cp.async.commit_group;")
#define CP_WAIT1()  asm volatile("cp.async.wait_group 1;")
#define CP_WAIT0()  asm volatile("cp.async.wait_group 0;")

__device__ __forceinline__ float4 bf4_to_f32(uint2 t) {
    __nv_bfloat162 a = *reinterpret_cast<__nv_bfloat162*>(&t.x);
    __nv_bfloat162 b = *reinterpret_cast<__nv_bfloat162*>(&t.y);
    float2 fa = __bfloat1622float2(a);
    float2 fb = __bfloat1622float2(b);
    return make_float4(fa.x, fa.y, fb.x, fb.y);
}

// ---------------- CSR build --------------------------------------------------
__global__ void zero_cnt_kernel() {
    int i = blockIdx.x * blockDim.x + threadIdx.x;
    if (i < N_NODES) g_cnt[i] = 0;
}

__global__ void deg_count_kernel(const int* __restrict__ dst) {
    int e = blockIdx.x * blockDim.x + threadIdx.x;
    if (e < N_EDGES) atomicAdd(&g_cnt[dst[e]], 1);
}

__global__ void deg_finalize_kernel() {
    int i = blockIdx.x * blockDim.x + threadIdx.x;
    if (i < N_NODES) g_dinv[i] = rsqrtf((float)g_cnt[i] + 1.0f);  // +1 self-loop
}

__global__ __launch_bounds__(SCAN_B)
void scanA_kernel() {
    __shared__ int sh[SCAN_B / 32];
    int idx = blockIdx.x * SCAN_B + threadIdx.x;
    int v = (idx < N_NODES) ? g_cnt[idx] : 0;
#pragma unroll
    for (int d = 16; d > 0; d >>= 1) v += __shfl_down_sync(~0u, v, d);
    if ((threadIdx.x & 31) == 0) sh[threadIdx.x >> 5] = v;
    __syncthreads();
    if (threadIdx.x < SCAN_B / 32) {
        int s = sh[threadIdx.x];
#pragma unroll
        for (int d = SCAN_B / 64; d > 0; d >>= 1) s += __shfl_down_sync(~0u, s, d);
        if (threadIdx.x == 0) g_blksum[blockIdx.x] = s;
    }
}

__global__ __launch_bounds__(SCAN_B)
void scanB_kernel() {
    __shared__ int sh[SCAN_B];
    int t = threadIdx.x;
    int v = (t < SCAN_NBLK) ? g_blksum[t] : 0;
    sh[t] = v;
    __syncthreads();
    for (int d = 1; d < SCAN_B; d <<= 1) {
        int u = (t >= d) ? sh[t - d] : 0;
        __syncthreads();
        sh[t] += u;
        __syncthreads();
    }
    if (t < SCAN_NBLK) g_blksum[t] = sh[t] - v;   // exclusive
}

__global__ __launch_bounds__(SCAN_B)
void scanC_kernel() {
    __shared__ int sh[SCAN_B];
    int t = threadIdx.x;
    int idx = blockIdx.x * SCAN_B + t;
    int v = (idx < N_NODES) ? g_cnt[idx] : 0;
    sh[t] = v;
    __syncthreads();
    for (int d = 1; d < SCAN_B; d <<= 1) {
        int u = (t >= d) ? sh[t - d] : 0;
        __syncthreads();
        sh[t] += u;
        __syncthreads();
    }
    if (idx < N_NODES) {
        int off = g_blksum[blockIdx.x] + sh[t] - v;
        g_off[idx] = off;
        g_cur[idx] = off;
    }
}

__global__ void fill_kernel(const int* __restrict__ src,
                            const int* __restrict__ dst) {
    int e = blockIdx.x * blockDim.x + threadIdx.x;
    if (e >= N_EDGES) return;
    int pos = atomicAdd(&g_cur[dst[e]], 1);
    g_csr_src[pos] = src[e];
}

// ---------------- tf32 tensor GEMM (cp.async 2-stage pipeline) --------------
// BM=128, BN=128, BK=32; 8 warps, warp tile 64x32. Output bf16.
#define AS_LD 36
#define BS_LD 132
struct GemmSmem {
    float As[2][128][AS_LD];
    float Bs[2][32][BS_LD];
};

__global__ __launch_bounds__(256, 2)
void tf32_gemm_kernel(const float* __restrict__ A, const float* __restrict__ B,
                      __nv_bfloat16* __restrict__ Cb, int M, int N, int K) {
    extern __shared__ char smem_raw[];
    GemmSmem& sm = *reinterpret_cast<GemmSmem*>(smem_raw);

    int tid  = threadIdx.x;
    int m0   = blockIdx.x * 128;
    int n0   = blockIdx.y * 128;
    int wid  = tid >> 5;
    int lane = tid & 31;
    int wm = (wid & 1) * 64;
    int wn = (wid >> 1) * 32;
    int lq = lane >> 2;
    int lr = lane & 3;

    float c[4][4][4];
#pragma unroll
    for (int i = 0; i < 4; i++)
#pragma unroll
        for (int j = 0; j < 4; j++)
#pragma unroll
            for (int r = 0; r < 4; r++) c[i][j][r] = 0.0f;

    int a_r = tid >> 3;             // 0..31 (stride 32)
    int a_c = (tid & 7) * 4;        // 0..28
    int b_r = tid >> 5;             // 0..7  (stride 8)
    int b_c = (tid & 31) * 4;       // 0..124

    auto issue_tile = [&](int k0, int buf) {
#pragma unroll
        for (int p = 0; p < 4; p++) {
            int r = a_r + p * 32;
            bool valid = (m0 + r) < M;
            const float* gp = A + (size_t)(valid ? (m0 + r) : 0) * K + k0 + a_c;
            cp_async16(&sm.As[buf][r][a_c], gp, valid);
        }
#pragma unroll
        for (int p = 0; p < 4; p++) {
            int r = b_r + p * 8;
            cp_async16(&sm.Bs[buf][r][b_c], B + (size_t)(k0 + r) * N + n0 + b_c, true);
        }
    };

    const int nk = K / 32;
    issue_tile(0, 0);
    CP_COMMIT();

    for (int it = 0; it < nk; it++) {
        if (it + 1 < nk) {
            issue_tile((it + 1) * 32, (it + 1) & 1);
            CP_COMMIT();
            CP_WAIT1();
        } else {
            CP_WAIT0();
        }
        __syncthreads();

        int buf = it & 1;
#pragma unroll
        for (int kk = 0; kk < 4; kk++) {
            int k = kk * 8;
            uint32_t a[4][4], b[4][2];
#pragma unroll
            for (int i = 0; i < 4; i++) {
                int r = wm + i * 16 + lq;
                a[i][0] = tf32u(sm.As[buf][r    ][k + lr    ]);
                a[i][1] = tf32u(sm.As[buf][r + 8][k + lr    ]);
                a[i][2] = tf32u(sm.As[buf][r    ][k + lr + 4]);
                a[i][3] = tf32u(sm.As[buf][r + 8][k + lr + 4]);
            }
#pragma unroll
            for (int j = 0; j < 4; j++) {
                int cc = wn + j * 8 + lq;
                b[j][0] = tf32u(sm.Bs[buf][k + lr    ][cc]);
                b[j][1] = tf32u(sm.Bs[buf][k + lr + 4][cc]);
            }
#pragma unroll
            for (int i = 0; i < 4; i++)
#pragma unroll
                for (int j = 0; j < 4; j++)
                    mma_tf32(c[i][j], a[i], b[j]);
        }
        __syncthreads();
    }

#pragma unroll
    for (int i = 0; i < 4; i++) {
        int r0 = m0 + wm + i * 16 + lq;
        int r1 = r0 + 8;
#pragma unroll
        for (int j = 0; j < 4; j++) {
            int col = n0 + wn + j * 8 + 2 * lr;
            if (r0 < M)
                *(__nv_bfloat162*)(Cb + (size_t)r0 * N + col) =
                    __float22bfloat162_rn(make_float2(c[i][j][0], c[i][j][1]));
            if (r1 < M)
                *(__nv_bfloat162*)(Cb + (size_t)r1 * N + col) =
                    __float22bfloat162_rn(make_float2(c[i][j][2], c[i][j][3]));
        }
    }
}

// ---------------- CSR gather (bf16 input, fp32 accumulate/output) ----------
// warp per dst node; V = C/128 uint2 chunks (4 channels) per lane
template <int C, bool RELU>
__global__ void gather_kernel(const __nv_bfloat16* __restrict__ h,
                              float* __restrict__ outp,
                              const float* __restrict__ bias) {
    int node = (blockIdx.x * blockDim.x + threadIdx.x) >> 5;
    int lane = threadIdx.x & 31;
    if (node >= N_NODES) return;
    const int V  = C / 128;            // uint2 chunks per lane
    const int RS = C / 4;              // row stride in uint2

    float dd = g_dinv[node];
    float w  = dd * dd;

    const uint2* hb = (const uint2*)h;

    float4 acc[V];
#pragma unroll
    for (int v = 0; v < V; v++) {
        float4 t = bf4_to_f32(hb[(size_t)node * RS + lane + 32 * v]);
        acc[v] = make_float4(t.x * w, t.y * w, t.z * w, t.w * w);
    }

    int j   = g_off[node];
    int end = j + g_cnt[node];

    // unroll-by-4 for memory-level parallelism
    for (; j + 3 < end; j += 4) {
        int s0 = g_csr_src[j],     s1 = g_csr_src[j + 1];
        int s2 = g_csr_src[j + 2], s3 = g_csr_src[j + 3];
        float n0 = g_dinv[s0] * dd, n1 = g_dinv[s1] * dd;
        float n2 = g_dinv[s2] * dd, n3 = g_dinv[s3] * dd;
        const uint2* h0 = hb + (size_t)s0 * RS;
        const uint2* h1 = hb + (size_t)s1 * RS;
        const uint2* h2 = hb + (size_t)s2 * RS;
        const uint2* h3 = hb + (size_t)s3 * RS;
#pragma unroll
        for (int v = 0; v < V; v++) {
            int idx = lane + 32 * v;
            float4 t0 = bf4_to_f32(h0[idx]);
            float4 t1 = bf4_to_f32(h1[idx]);
            float4 t2 = bf4_to_f32(h2[idx]);
            float4 t3 = bf4_to_f32(h3[idx]);
            acc[v].x += t0.x * n0; acc[v].y += t0.y * n0;
            acc[v].z += t0.z * n0; acc[v].w += t0.w * n0;
            acc[v].x += t1.x * n1; acc[v].y += t1.y * n1;
            acc[v].z += t1.z * n1; acc[v].w += t1.w * n1;
            acc[v].x += t2.x * n2; acc[v].y += t2.y * n2;
            acc[v].z += t2.z * n2; acc[v].w += t2.w * n2;
            acc[v].x += t3.x * n3; acc[v].y += t3.y * n3;
            acc[v].z += t3.z * n3; acc[v].w += t3.w * n3;
        }
    }
    for (; j < end; j++) {
        int s0 = g_csr_src[j];
        float n0 = g_dinv[s0] * dd;
        const uint2* h0 = hb + (size_t)s0 * RS;
#pragma unroll
        for (int v = 0; v < V; v++) {
            float4 t0 = bf4_to_f32(h0[lane + 32 * v]);
            acc[v].x += t0.x * n0; acc[v].y += t0.y * n0;
            acc[v].z += t0.z * n0; acc[v].w += t0.w * n0;
        }
    }

    float4* op = (float4*)(outp + (size_t)node * C);
#pragma unroll
    for (int v = 0; v < V; v++) {
        const float4 b = ((const float4*)bias)[lane + 32 * v];
        float4 o = acc[v];
        o.x += b.x; o.y += b.y; o.z += b.z; o.w += b.w;
        if (RELU) {
            o.x = fmaxf(o.x, 0.f); o.y = fmaxf(o.y, 0.f);
            o.z = fmaxf(o.z, 0.f); o.w = fmaxf(o.w, 0.f);
        }
        op[lane + 32 * v] = o;
    }
}

// ---------------- launch ----------------------------------------------------
extern "C" void kernel_launch(void* const* d_in, const int* in_sizes, int n_in,
                              void* d_out, int out_size) {
    const float* x  = (const float*)d_in[0];
    const int*   ei = (const int*)d_in[1];     // int32: JAX x64 disabled
    const float* W1 = (const float*)d_in[2];
    const float* b1 = (const float*)d_in[3];
    const float* W2 = (const float*)d_in[4];
    const float* b2 = (const float*)d_in[5];
    float* out = (float*)d_out;

    const int* src = ei;
    const int* dst = ei + N_EDGES;

    __nv_bfloat16* g_h_p;   cudaGetSymbolAddress((void**)&g_h_p,   g_h);
    float*         g_agg_p; cudaGetSymbolAddress((void**)&g_agg_p, g_agg);
    __nv_bfloat16* g_h2_p;  cudaGetSymbolAddress((void**)&g_h2_p,  g_h2);

    const int gemm_smem = sizeof(GemmSmem);           // ~69 KB
    static bool attr_set = false;
    if (!attr_set) {
        cudaFuncSetAttribute(tf32_gemm_kernel,
                             cudaFuncAttributeMaxDynamicSharedMemorySize, gemm_smem);
        attr_set = true;
    }

    // 1) CSR build + dinv
    zero_cnt_kernel<<<(N_NODES + 255) / 256, 256>>>();
    deg_count_kernel<<<(N_EDGES + 255) / 256, 256>>>(dst);
    deg_finalize_kernel<<<(N_NODES + 255) / 256, 256>>>();
    scanA_kernel<<<SCAN_NBLK, SCAN_B>>>();
    scanB_kernel<<<1, SCAN_B>>>();
    scanC_kernel<<<SCAN_NBLK, SCAN_B>>>();
    fill_kernel<<<(N_EDGES + 255) / 256, 256>>>(src, dst);

    // 2) h = x @ W1  (bf16 out)
    {
        dim3 grid((N_NODES + 127) / 128, H1 / 128);
        tf32_gemm_kernel<<<grid, 256, gemm_smem>>>(x, W1, g_h_p, N_NODES, H1, NFEAT);
    }

    // 3) h1 = relu(aggregate(h) + b1)  (fp32 out)
    gather_kernel<H1, true><<<(N_NODES * 32 + 255) / 256, 256>>>(g_h_p, g_agg_p, b1);

    // 4) h2 = h1 @ W2  (bf16 out)
    {
        dim3 grid((N_NODES + 127) / 128, H2 / 128);
        tf32_gemm_kernel<<<grid, 256, gemm_smem>>>(g_agg_p, W2, g_h2_p, N_NODES, H2, H1);
    }

    // 5) out = aggregate(h2) + b2  (fp32 out)
    gather_kernel<H2, false><<<(N_NODES * 32 + 255) / 256, 256>>>(g_h2_p, out, b2);
}